// round 12
// baseline (speedup 1.0000x reference)
#include <cuda_runtime.h>
#include <cuda_fp16.h>
#include <math.h>
#include <stdint.h>

// ---------------- problem constants ----------------
#define NB 8
#define NL 2048
#define NLP1 2049
#define NH 512
#define NHEADS 8
#define HDIM 64
#define NLAYERS 4

#define MPAD 16512          // 129*128 row capacity (A padding for cp.async)
#define QS 1536             // fused qkv row stride (fp32)
#define MH 8192             // row split point (64 tiles)

// ---------------- scratch (device globals; no allocation) ----------------
__device__ float g_nodes[(size_t)NB * NL * NH];            // 32 MB
__device__ float g_qkv [(size_t)NB * NLP1 * QS];           // 100 MB (fp32)
__device__ float g_relay[NB * NH];
__device__ float g_attr [NB * NH];
__device__ float g_part [(size_t)NB * 32 * NH];
__device__ __align__(16) __half g_a16[(size_t)MPAD * NH];  // 16.9 MB (GEMM A operand)
__device__ __align__(16) __half g_b16[(size_t)(512 + NLAYERS * 2048) * NH]; // 8.9 MB

// =====================================================================
//  low-level helpers
// =====================================================================
__device__ __forceinline__ uint32_t smem_u32(const void* p) {
    uint32_t a;
    asm("{ .reg .u64 t; cvta.to.shared.u64 t, %1; cvt.u32.u64 %0, t; }"
        : "=r"(a) : "l"(p));
    return a;
}

#define CP_ASYNC16(dst, src) \
    asm volatile("cp.async.cg.shared.global [%0], [%1], 16;" \
        :: "r"(dst), "l"(src) : "memory")
#define CP_COMMIT() asm volatile("cp.async.commit_group;" ::: "memory")
#define CP_WAIT(n)  asm volatile("cp.async.wait_group %0;" :: "n"(n) : "memory")

__device__ __forceinline__ void ldsm4(uint32_t* r, uint32_t addr) {
    asm volatile("ldmatrix.sync.aligned.m8n8.x4.shared.b16 {%0,%1,%2,%3}, [%4];"
        : "=r"(r[0]), "=r"(r[1]), "=r"(r[2]), "=r"(r[3]) : "r"(addr));
}

__device__ __forceinline__ void mma16816f(float* c, const uint32_t* a, const uint32_t* b) {
    asm volatile("mma.sync.aligned.m16n8k16.row.col.f32.f16.f16.f32 "
        "{%0,%1,%2,%3}, {%4,%5,%6,%7}, {%8,%9}, {%0,%1,%2,%3};"
        : "+f"(c[0]), "+f"(c[1]), "+f"(c[2]), "+f"(c[3])
        : "r"(a[0]), "r"(a[1]), "r"(a[2]), "r"(a[3]), "r"(b[0]), "r"(b[1]));
}

// swizzled byte offset within one stage tile: 128 rows x 64B (4 chunks of 16B)
__device__ __forceinline__ uint32_t swz(int row, int chunk) {
    return (uint32_t)(row * 64 + ((chunk ^ ((row >> 1) & 3)) << 4));
}

// =====================================================================
//  fp16 mma.sync GEMM (identical numerics to R7 kernel)
//  EPI 0: +bias +pos_emb ; 1: +bias ; 2: leaky(+bias)
// =====================================================================
#define STG 4
#define STAGE_BYTES 8192
#define SMEM_GEMM (2 * STG * STAGE_BYTES)
#define KBLKS 16

template<int EPI>
__global__ void __launch_bounds__(256, 2)
mmagemm16(const __half* __restrict__ A, const __half* __restrict__ Bt,
          const float* __restrict__ b0p, const float* __restrict__ b1p,
          const float* __restrict__ b2p, const float* __restrict__ extra,
          float* __restrict__ C, int M, int CS)
{
    extern __shared__ char smem[];
    const uint32_t aBase = smem_u32(smem);
    const uint32_t bBase = aBase + STG * STAGE_BYTES;
    const int tid = threadIdx.x, wid = tid >> 5, lane = tid & 31;
    const int nt = blockIdx.x, mt = blockIdx.y;
    const int warpM = wid & 3, warpN = wid >> 2;

    const int lrow = tid >> 2, lch = tid & 3;
    const __half* ag0 = A + (size_t)(mt * 128 + lrow) * NH + lch * 8;
    const __half* bg0 = Bt + (size_t)(nt * 128 + lrow) * NH + lch * 8;
    const uint32_t sA0 = swz(lrow, lch), sA1 = swz(lrow + 64, lch);

#define LOAD_STAGE(kb, stg) do { \
    const __half* _ag = ag0 + (kb) * 32; \
    const __half* _bg = bg0 + (kb) * 32; \
    uint32_t _da = aBase + (stg) * STAGE_BYTES; \
    uint32_t _db = bBase + (stg) * STAGE_BYTES; \
    CP_ASYNC16(_da + sA0, _ag); \
    CP_ASYNC16(_da + sA1, _ag + (size_t)64 * NH); \
    CP_ASYNC16(_db + sA0, _bg); \
    CP_ASYNC16(_db + sA1, _bg + (size_t)64 * NH); \
    CP_COMMIT(); \
} while (0)

    LOAD_STAGE(0, 0);
    LOAD_STAGE(1, 1);
    LOAD_STAGE(2, 2);

    const int lr = lane & 7;
    const int aRowB = warpM * 32 + lr + ((lane >> 3) & 1) * 8;
    const int aChB  = (lane >> 4);
    const int bRowB = warpN * 64 + lr + (lane >> 4) * 8;
    const int bChB  = (lane >> 3) & 1;

    float acc[64];
#pragma unroll
    for (int i = 0; i < 64; i++) acc[i] = 0.f;

    for (int kb = 0; kb < KBLKS; kb++) {
        const int stg = kb & 3;
        CP_WAIT(2);
        __syncthreads();
        if (kb + 3 < KBLKS) LOAD_STAGE(kb + 3, (kb + 3) & 3);

        const uint32_t da = aBase + stg * STAGE_BYTES;
        const uint32_t db = bBase + stg * STAGE_BYTES;
#pragma unroll
        for (int ks = 0; ks < 2; ks++) {
            uint32_t af[2][4];
#pragma unroll
            for (int mi = 0; mi < 2; mi++)
                ldsm4(af[mi], da + swz(aRowB + mi * 16, ks * 2 + aChB));
#pragma unroll
            for (int p = 0; p < 4; p++) {
                uint32_t bf[4];
                ldsm4(bf, db + swz(bRowB + p * 16, ks * 2 + bChB));
#pragma unroll
                for (int mi = 0; mi < 2; mi++) {
                    mma16816f(&acc[(mi * 8 + 2 * p + 0) * 4], af[mi], bf + 0);
                    mma16816f(&acc[(mi * 8 + 2 * p + 1) * 4], af[mi], bf + 2);
                }
            }
        }
        __syncthreads();
    }

#pragma unroll
    for (int mi = 0; mi < 2; mi++) {
#pragma unroll
        for (int ntile = 0; ntile < 8; ntile++) {
            const float* c = &acc[(mi * 8 + ntile) * 4];
            int row0 = mt * 128 + warpM * 32 + mi * 16 + (lane >> 2);
            int col  = nt * 128 + warpN * 64 + ntile * 8 + (lane & 3) * 2;
            int seg = col >> 9;
            const float* bp = (seg == 0) ? b0p : (seg == 1) ? b1p : b2p;
            int cl = col & 511;
            float bb0 = bp[cl], bb1 = bp[cl + 1];
#pragma unroll
            for (int half0 = 0; half0 < 2; half0++) {
                int row = row0 + half0 * 8;
                if (row >= M) continue;
                float2 o;
                o.x = c[half0 * 2 + 0] + bb0;
                o.y = c[half0 * 2 + 1] + bb1;
                if (EPI == 0) {
                    const float* e = extra + (size_t)(row & (NL - 1)) * NH + col;
                    o.x += e[0]; o.y += e[1];
                }
                if (EPI == 2) {
                    o.x = o.x > 0.f ? o.x : 0.2f * o.x;
                    o.y = o.y > 0.f ? o.y : 0.2f * o.y;
                }
                *(float2*)(C + (size_t)row * CS + col) = o;
            }
        }
    }
#undef LOAD_STAGE
}

// ---------------- A conversion: fp32 -> fp16 (for `data` only) --------------
__global__ __launch_bounds__(256) void convA16_k(const float* __restrict__ in,
                                                 __half* __restrict__ out, int n4)
{
    int i = blockIdx.x * 256 + threadIdx.x;
    if (i >= n4) return;
    float4 x = ((const float4*)in)[i];
    ((__half2*)out)[i * 2]     = __floats2half2_rn(x.x, x.y);
    ((__half2*)out)[i * 2 + 1] = __floats2half2_rn(x.z, x.w);
}

// ---------------- ALL weight transposes -> fp16 in ONE launch ---------------
__global__ __launch_bounds__(256) void convB_all_k(
    const float* __restrict__ fc_w, const float* __restrict__ wq,
    const float* __restrict__ wk,   const float* __restrict__ wv,
    const float* __restrict__ wo,   __half* __restrict__ b16)
{
    __shared__ float t[32][33];
    int s = blockIdx.z;
    const float* W;
    __half* Bt;
    if (s == 0) {
        W = fc_w; Bt = b16;
    } else {
        int i = (s - 1) >> 2, j = (s - 1) & 3;
        const float* src = (j == 0) ? wq : (j == 1) ? wk : (j == 2) ? wv : wo;
        W  = src + (size_t)i * NH * NH;
        Bt = b16 + (size_t)(512 + i * 2048 + j * 512) * NH;
    }
    int k0 = blockIdx.x * 32, n0 = blockIdx.y * 32;
    int tx = threadIdx.x & 31, ty = threadIdx.x >> 5;
#pragma unroll
    for (int i = 0; i < 32; i += 8)
        t[ty + i][tx] = W[(size_t)(k0 + ty + i) * NH + n0 + tx];
    __syncthreads();
#pragma unroll
    for (int i = 0; i < 32; i += 8) {
        int n = n0 + ty + i, k = k0 + tx;
        Bt[(size_t)n * NH + k] = __float2half_rn(t[tx][ty + i]);
    }
}

// ---------------- relay mean, two-phase ----------------
__global__ void relay_part_k(const float* __restrict__ embs, float* __restrict__ part)
{
    int b = blockIdx.y, ch = blockIdx.x, j = threadIdx.x;
    const float* p = embs + ((size_t)b * NL + ch * 64) * NH + j;
    float s = 0.f;
#pragma unroll 8
    for (int l = 0; l < 64; l++) s += p[(size_t)l * NH];
    part[((size_t)b * 32 + ch) * NH + j] = s;
}
__global__ void relay_fin_k(const float* __restrict__ part, float* __restrict__ relay)
{
    int b = blockIdx.x, j = threadIdx.x;
    float s = 0.f;
#pragma unroll
    for (int c = 0; c < 32; c++) s += part[((size_t)b * 32 + c) * NH + j];
    relay[b * NH + j] = s * (1.f / NL);
}

// ---------------- LayerNorm + concat relay -> a16 (fp16), row-offset --------
__global__ __launch_bounds__(256) void ln_concat_k(
    const float* __restrict__ nodes, const float* __restrict__ relay,
    const float* __restrict__ gamma, const float* __restrict__ beta,
    __half* __restrict__ a16, int row0)
{
    __shared__ float2 sh[8];
    int row = blockIdx.x + row0;
    int b = row / NLP1, l = row - b * NLP1;
    int tid = threadIdx.x;
    __half2* dst = (__half2*)(a16 + (size_t)row * NH);

    if (l == NL) {
        float2 x = ((const float2*)(relay + b * NH))[tid];
        dst[tid] = __floats2half2_rn(x.x, x.y);
        return;
    }
    float2 x = ((const float2*)(nodes + ((size_t)b * NL + l) * NH))[tid];
    float2 v = make_float2(x.x + x.y, x.x * x.x + x.y * x.y);
    int lane = tid & 31, w = tid >> 5;
#pragma unroll
    for (int o = 16; o; o >>= 1) {
        v.x += __shfl_xor_sync(0xffffffffu, v.x, o);
        v.y += __shfl_xor_sync(0xffffffffu, v.y, o);
    }
    if (lane == 0) sh[w] = v;
    __syncthreads();
    if (tid == 0) {
        float2 t = sh[0];
#pragma unroll
        for (int i = 1; i < 8; i++) { t.x += sh[i].x; t.y += sh[i].y; }
        sh[0] = t;
    }
    __syncthreads();
    float2 t = sh[0];
    float mu = t.x * (1.f / NH);
    float var = t.y * (1.f / NH) - mu * mu;
    float inv = rsqrtf(var + 1e-6f);
    float2 g = ((const float2*)gamma)[tid];
    float2 bb = ((const float2*)beta)[tid];
    float ox = (x.x - mu) * inv * g.x + bb.x;
    float oy = (x.y - mu) * inv * g.y + bb.y;
    dst[tid] = __floats2half2_rn(ox, oy);
}

// ---------------- ring attention (fp32 qkv) -> a16 (fp16), block-offset -----
// one block per (b,l) row; 8 warps = 8 heads
__global__ __launch_bounds__(256) void ring_attn_k(
    const float* __restrict__ qkv, __half* __restrict__ a16, int blk0)
{
    int gw = (blockIdx.x + blk0) * 8 + (threadIdx.x >> 5);
    int lane = threadIdx.x & 31;
    int h = gw & 7;
    int l = (gw >> 3) & (NL - 1);
    int b = gw >> 14;
    size_t rb = (size_t)b * NLP1 * QS + (size_t)h * HDIM + lane * 2;
    float2 qv = *(const float2*)(qkv + rb + (size_t)l * QS);

    const float* kk = qkv + rb + 512;
    const float* vv = qkv + rb + 1024;
    float2 z = make_float2(0.f, 0.f);
    float2 km = (l > 0)      ? *(const float2*)(kk + (size_t)(l - 1) * QS) : z;
    float2 kc =                *(const float2*)(kk + (size_t)l       * QS);
    float2 kp = (l < NL - 1) ? *(const float2*)(kk + (size_t)(l + 1) * QS) : z;
    float2 kr =                *(const float2*)(kk + (size_t)NL      * QS);
    float s0 = qv.x * km.x + qv.y * km.y;
    float s1 = qv.x * kc.x + qv.y * kc.y;
    float s2 = qv.x * kp.x + qv.y * kp.y;
    float s3 = qv.x * kr.x + qv.y * kr.y;
#pragma unroll
    for (int o = 16; o; o >>= 1) {
        s0 += __shfl_xor_sync(0xffffffffu, s0, o);
        s1 += __shfl_xor_sync(0xffffffffu, s1, o);
        s2 += __shfl_xor_sync(0xffffffffu, s2, o);
        s3 += __shfl_xor_sync(0xffffffffu, s3, o);
    }
    const float scale = 0.125f;
    s0 *= scale; s1 *= scale; s2 *= scale; s3 *= scale;
    float m = fmaxf(fmaxf(s0, s1), fmaxf(s2, s3));
    float e0 = __expf(s0 - m), e1 = __expf(s1 - m);
    float e2 = __expf(s2 - m), e3 = __expf(s3 - m);
    float inv = 1.f / (e0 + e1 + e2 + e3);
    float2 vm = (l > 0)      ? *(const float2*)(vv + (size_t)(l - 1) * QS) : z;
    float2 vc =                *(const float2*)(vv + (size_t)l       * QS);
    float2 vp = (l < NL - 1) ? *(const float2*)(vv + (size_t)(l + 1) * QS) : z;
    float2 vr =                *(const float2*)(vv + (size_t)NL      * QS);
    float ox = (e0 * vm.x + e1 * vc.x + e2 * vp.x + e3 * vr.x) * inv;
    float oy = (e0 * vm.y + e1 * vc.y + e2 * vp.y + e3 * vr.y) * inv;

    __half2* dst = (__half2*)(a16 + ((size_t)b * NL + l) * NH + (size_t)h * HDIM);
    dst[lane] = __floats2half2_rn(ox, oy);
}

// ---------------- star attention (fp32 qkv) ----------------
__global__ __launch_bounds__(256) void star_attn_k(
    const float* __restrict__ qkv, float* __restrict__ attr)
{
    __shared__ float sq[HDIM];
    __shared__ float sc[NLP1];
    __shared__ float red[8];
    __shared__ float part[4][HDIM];
    int b = blockIdx.x >> 3, h = blockIdx.x & 7;
    int tid = threadIdx.x;
    size_t hb = (size_t)b * NLP1 * QS + (size_t)h * HDIM;
    if (tid < HDIM) sq[tid] = qkv[hb + (size_t)NL * QS + tid];
    __syncthreads();
    float lmax = -1e30f;
    for (int l = tid; l < NLP1; l += 256) {
        const float4* kp = (const float4*)(qkv + hb + 512 + (size_t)l * QS);
        float d = 0.f;
#pragma unroll
        for (int j = 0; j < HDIM / 4; j++) {
            float4 kk = kp[j];
            d += sq[4 * j + 0] * kk.x + sq[4 * j + 1] * kk.y
               + sq[4 * j + 2] * kk.z + sq[4 * j + 3] * kk.w;
        }
        d *= 0.125f;
        sc[l] = d;
        lmax = fmaxf(lmax, d);
    }
    int lane = tid & 31, w = tid >> 5;
#pragma unroll
    for (int o = 16; o; o >>= 1) lmax = fmaxf(lmax, __shfl_xor_sync(0xffffffffu, lmax, o));
    if (lane == 0) red[w] = lmax;
    __syncthreads();
    if (tid == 0) {
        float m = red[0];
#pragma unroll
        for (int i = 1; i < 8; i++) m = fmaxf(m, red[i]);
        red[0] = m;
    }
    __syncthreads();
    float m = red[0];
    __syncthreads();
    float lsum = 0.f;
    for (int l = tid; l < NLP1; l += 256) {
        float e = __expf(sc[l] - m);
        sc[l] = e;
        lsum += e;
    }
#pragma unroll
    for (int o = 16; o; o >>= 1) lsum += __shfl_xor_sync(0xffffffffu, lsum, o);
    if (lane == 0) red[w] = lsum;
    __syncthreads();
    if (tid == 0) {
        float s = 0.f;
#pragma unroll
        for (int i = 0; i < 8; i++) s += red[i];
        red[0] = s;
    }
    __syncthreads();
    float Zinv = 1.f / red[0];
    int d = tid & 63, g = tid >> 6;
    float acc = 0.f;
    for (int l = g; l < NLP1; l += 4)
        acc += sc[l] * qkv[hb + 1024 + (size_t)l * QS + d];
    part[g][d] = acc;
    __syncthreads();
    if (tid < HDIM)
        attr[(size_t)b * NH + h * HDIM + tid] =
            (part[0][tid] + part[1][tid] + part[2][tid] + part[3][tid]) * Zinv;
}

// ---------------- star output GEMM + leaky ----------------
__global__ __launch_bounds__(256) void star_out_k(
    const float* __restrict__ attr, const float* __restrict__ w,
    const float* __restrict__ bias, float* __restrict__ relay)
{
    __shared__ float sa[512];
    __shared__ float red[4][64];
    int b = blockIdx.y, cx = blockIdx.x;
    int t = threadIdx.x;
    sa[t]       = attr[b * NH + t];
    sa[t + 256] = attr[b * NH + t + 256];
    __syncthreads();
    int col = cx * 64 + (t & 63), g = t >> 6;
    float acc = 0.f;
    const float* wp = w + (size_t)(g * 128) * NH + col;
#pragma unroll 4
    for (int kk = 0; kk < 128; kk++)
        acc += sa[g * 128 + kk] * wp[(size_t)kk * NH];
    red[g][t & 63] = acc;
    __syncthreads();
    if (t < 64) {
        float a = red[0][t] + red[1][t] + red[2][t] + red[3][t] + bias[cx * 64 + t];
        relay[b * NH + cx * 64 + t] = a > 0.f ? a : 0.2f * a;
    }
}

// ---------------- final max, two-phase ----------------
__global__ void final_part_k(const float* __restrict__ nodes, float* __restrict__ part)
{
    int b = blockIdx.y, ch = blockIdx.x, j = threadIdx.x;
    const float* p = nodes + ((size_t)b * NL + ch * 64) * NH + j;
    float m = -3.4e38f;
#pragma unroll 8
    for (int l = 0; l < 64; l++) m = fmaxf(m, p[(size_t)l * NH]);
    part[((size_t)b * 32 + ch) * NH + j] = m;
}
__global__ void final_fin_k(const float* __restrict__ part,
                            const float* __restrict__ relay, float* __restrict__ out)
{
    int b = blockIdx.x, j = threadIdx.x;
    float m = -3.4e38f;
#pragma unroll
    for (int c = 0; c < 32; c++) m = fmaxf(m, part[((size_t)b * 32 + c) * NH + j]);
    out[b * NH + j] = 0.5f * (relay[b * NH + j] + m);
}

// =====================================================================
//  host launch
// =====================================================================
extern "C" void kernel_launch(void* const* d_in, const int* in_sizes, int n_in,
                              void* d_out, int out_size)
{
    const float* data    = (const float*)d_in[0];
    const float* fc_w    = (const float*)d_in[1];
    const float* fc_b    = (const float*)d_in[2];
    const float* pos_emb = (const float*)d_in[3];
    const float* ln_g    = (const float*)d_in[4];
    const float* ln_b    = (const float*)d_in[5];
    const float* wq      = (const float*)d_in[6];
    const float* wk      = (const float*)d_in[7];
    const float* wv      = (const float*)d_in[8];
    const float* bq      = (const float*)d_in[9];
    const float* bk      = (const float*)d_in[10];
    const float* bv      = (const float*)d_in[11];
    const float* ring_wo = (const float*)d_in[12];
    const float* ring_bo = (const float*)d_in[13];
    const float* star_wo = (const float*)d_in[14];
    const float* star_bo = (const float*)d_in[15];
    float* out = (float*)d_out;

    float *nodes, *qkv, *relay, *attr, *part;
    __half *a16, *b16;
    cudaGetSymbolAddress((void**)&nodes, g_nodes);
    cudaGetSymbolAddress((void**)&qkv,   g_qkv);
    cudaGetSymbolAddress((void**)&relay, g_relay);
    cudaGetSymbolAddress((void**)&attr,  g_attr);
    cudaGetSymbolAddress((void**)&part,  g_part);
    cudaGetSymbolAddress((void**)&a16,   g_a16);
    cudaGetSymbolAddress((void**)&b16,   g_b16);

    static bool init_done = false;
    static cudaStream_t s2, s3;
    static cudaEvent_t evJoin[NLAYERS], evL1[NLAYERS], evQ[NLAYERS], evQ2[NLAYERS], evR1[NLAYERS];
    static cudaEvent_t evFork0, evConvB;
    if (!init_done) {
        cudaFuncSetAttribute(mmagemm16<0>, cudaFuncAttributeMaxDynamicSharedMemorySize, SMEM_GEMM);
        cudaFuncSetAttribute(mmagemm16<1>, cudaFuncAttributeMaxDynamicSharedMemorySize, SMEM_GEMM);
        cudaFuncSetAttribute(mmagemm16<2>, cudaFuncAttributeMaxDynamicSharedMemorySize, SMEM_GEMM);
        cudaStreamCreateWithFlags(&s2, cudaStreamNonBlocking);
        cudaStreamCreateWithFlags(&s3, cudaStreamNonBlocking);
        for (int i = 0; i < NLAYERS; i++) {
            cudaEventCreateWithFlags(&evJoin[i], cudaEventDisableTiming);
            cudaEventCreateWithFlags(&evL1[i],  cudaEventDisableTiming);
            cudaEventCreateWithFlags(&evQ[i],   cudaEventDisableTiming);
            cudaEventCreateWithFlags(&evQ2[i],  cudaEventDisableTiming);
            cudaEventCreateWithFlags(&evR1[i],  cudaEventDisableTiming);
        }
        cudaEventCreateWithFlags(&evFork0, cudaEventDisableTiming);
        cudaEventCreateWithFlags(&evConvB, cudaEventDisableTiming);
        init_done = true;
    }
    cudaStream_t s0 = (cudaStream_t)0;

    const int M_nodes = NB * NL;     // 16384
    const int M_xy    = NB * NLP1;   // 16392

    // ---- fork s2 from origin (graph-capture rule), convB on s2 ∥ convA on s0
    cudaEventRecord(evFork0, s0);
    cudaStreamWaitEvent(s2, evFork0, 0);
    convB_all_k<<<dim3(16, 16, 1 + NLAYERS * 4), 256, 0, s2>>>(fc_w, wq, wk, wv, ring_wo, b16);
    cudaEventRecord(evConvB, s2);
    convA16_k<<<(M_nodes * 128 + 255) / 256, 256>>>(data, a16, M_nodes * 128);
    cudaStreamWaitEvent(s0, evConvB, 0);

    // ---- embeddings (full, unsplit) ----
    mmagemm16<0><<<dim3(4, 128), 256, SMEM_GEMM>>>(a16, b16, fc_b, fc_b, fc_b, pos_emb,
                                                   nodes, M_nodes, NH);
    relay_part_k<<<dim3(32, NB), NH>>>(nodes, part);
    relay_fin_k<<<NB, NH>>>(part, relay);

    for (int i = 0; i < NLAYERS; i++) {
        size_t bOff = (size_t)i * 512;
        __half* slot  = b16 + (size_t)(512 + i * 2048) * NH;
        __half* slotO = slot + (size_t)1536 * NH;

        if (i > 0) cudaStreamWaitEvent(s0, evJoin[i - 1], 0);  // relay ready

        // --- ln split: rows [0,MH) on s0; rows [MH,M_xy) on s3 ---
        ln_concat_k<<<MH, 256, 0, s0>>>(nodes, relay, ln_g + bOff, ln_b + bOff, a16, 0);
        cudaEventRecord(evQ[i], s0);               // carries evJoin dep + ln h0
        cudaStreamWaitEvent(s3, evQ[i], 0);
        ln_concat_k<<<M_xy - MH, 256, 0, s3>>>(nodes, relay, ln_g + bOff, ln_b + bOff, a16, MH);
        cudaEventRecord(evL1[i], s3);

        // --- qkv GEMM: rows [0,MH) immediately; rows [MH,M_xy) after ln h1 ---
        mmagemm16<1><<<dim3(12, MH / 128), 256, SMEM_GEMM, s0>>>(
            a16, slot, bq + bOff, bk + bOff, bv + bOff, nullptr, qkv, MH, QS);
        cudaStreamWaitEvent(s0, evL1[i], 0);
        mmagemm16<1><<<dim3(12, (M_xy - MH + 127) / 128), 256, SMEM_GEMM, s0>>>(
            a16 + (size_t)MH * NH, slot, bq + bOff, bk + bOff, bv + bOff, nullptr,
            qkv + (size_t)MH * QS, M_xy - MH, QS);

        // --- fork after full qkv: star on s2, ring_attn half1 on s3 ---
        cudaEventRecord(evQ2[i], s0);
        cudaStreamWaitEvent(s2, evQ2[i], 0);
        star_attn_k<<<NB * NHEADS, 256, 0, s2>>>(qkv, attr);
        star_out_k<<<dim3(8, NB), 256, 0, s2>>>(attr, star_wo + (size_t)i * 512 * 512,
                                                star_bo + bOff, relay);
        cudaEventRecord(evJoin[i], s2);

        cudaStreamWaitEvent(s3, evQ2[i], 0);
        ring_attn_k<<<MH, 256, 0, s3>>>(qkv, a16, MH);       // att rows [MH,16384)
        cudaEventRecord(evR1[i], s3);

        // --- ring_attn half0 + ring GEMM half0 on s0, then half1 ---
        ring_attn_k<<<MH, 256, 0, s0>>>(qkv, a16, 0);        // att rows [0,MH)
        mmagemm16<2><<<dim3(4, MH / 128), 256, SMEM_GEMM, s0>>>(
            a16, slotO, ring_bo + bOff, ring_bo + bOff, ring_bo + bOff, nullptr,
            nodes, MH, NH);
        cudaStreamWaitEvent(s0, evR1[i], 0);
        mmagemm16<2><<<dim3(4, (M_nodes - MH) / 128), 256, SMEM_GEMM, s0>>>(
            a16 + (size_t)MH * NH, slotO, ring_bo + bOff, ring_bo + bOff, ring_bo + bOff,
            nullptr, nodes + (size_t)MH * NH, M_nodes - MH, NH);
    }

    final_part_k<<<dim3(32, NB), NH>>>(nodes, part);
    cudaStreamWaitEvent(s0, evJoin[NLAYERS - 1], 0);           // relay ready
    final_fin_k<<<NB, NH>>>(part, relay, out);
}

// round 13
// speedup vs baseline: 1.1060x; 1.1060x over previous
#include <cuda_runtime.h>
#include <cuda_fp16.h>
#include <math.h>
#include <stdint.h>

// ---------------- problem constants ----------------
#define NB 8
#define NL 2048
#define NLP1 2049
#define NH 512
#define NHEADS 8
#define HDIM 64
#define NLAYERS 4

#define MPAD 16512          // 129*128 row capacity (A padding for cp.async)
#define QS 1536             // fused qkv row stride (fp32)

// ---------------- scratch (device globals; no allocation) ----------------
__device__ float g_nodes[(size_t)NB * NL * NH];            // 32 MB
__device__ float g_qkv [(size_t)NB * NLP1 * QS];           // 100 MB (fp32)
__device__ float g_relay[NB * NH];
__device__ float g_attr [NB * NH];
__device__ float g_part [(size_t)NB * 32 * NH];
__device__ __align__(16) __half g_a16[(size_t)MPAD * NH];  // 16.9 MB (GEMM A operand)
__device__ __align__(16) __half g_b16[(size_t)(512 + NLAYERS * 2048) * NH]; // 8.9 MB

// =====================================================================
//  low-level helpers
// =====================================================================
__device__ __forceinline__ uint32_t smem_u32(const void* p) {
    uint32_t a;
    asm("{ .reg .u64 t; cvta.to.shared.u64 t, %1; cvt.u32.u64 %0, t; }"
        : "=r"(a) : "l"(p));
    return a;
}

#define CP_ASYNC16(dst, src) \
    asm volatile("cp.async.cg.shared.global [%0], [%1], 16;" \
        :: "r"(dst), "l"(src) : "memory")
#define CP_COMMIT() asm volatile("cp.async.commit_group;" ::: "memory")
#define CP_WAIT(n)  asm volatile("cp.async.wait_group %0;" :: "n"(n) : "memory")

__device__ __forceinline__ void ldsm4(uint32_t* r, uint32_t addr) {
    asm volatile("ldmatrix.sync.aligned.m8n8.x4.shared.b16 {%0,%1,%2,%3}, [%4];"
        : "=r"(r[0]), "=r"(r[1]), "=r"(r[2]), "=r"(r[3]) : "r"(addr));
}

__device__ __forceinline__ void mma16816f(float* c, const uint32_t* a, const uint32_t* b) {
    asm volatile("mma.sync.aligned.m16n8k16.row.col.f32.f16.f16.f32 "
        "{%0,%1,%2,%3}, {%4,%5,%6,%7}, {%8,%9}, {%0,%1,%2,%3};"
        : "+f"(c[0]), "+f"(c[1]), "+f"(c[2]), "+f"(c[3])
        : "r"(a[0]), "r"(a[1]), "r"(a[2]), "r"(a[3]), "r"(b[0]), "r"(b[1]));
}

// swizzled byte offset within one stage tile: 128 rows x 64B (4 chunks of 16B)
__device__ __forceinline__ uint32_t swz(int row, int chunk) {
    return (uint32_t)(row * 64 + ((chunk ^ ((row >> 1) & 3)) << 4));
}

// =====================================================================
//  fp16 mma.sync GEMM: C[M, CS-cols] = A[M,512] @ Bt[N,512]^T + epilogue
//  tile 128x128, 8 warps (4M x 2N), kblock 32, 4-stage cp.async.
//  Single leading __syncthreads per k-iteration (trailing barrier removed:
//  with 4 stages and wait_group(2), the leading sync at iter kb already
//  orders all reads of stage (kb-1)&3 before the cp.async that overwrites
//  that same physical stage for kb+3).
//  EPI 0: +bias +pos_emb ; 1: +bias ; 2: leaky(+bias)
// =====================================================================
#define STG 4
#define STAGE_BYTES 8192
#define SMEM_GEMM (2 * STG * STAGE_BYTES)
#define KBLKS 16

template<int EPI>
__global__ void __launch_bounds__(256, 2)
mmagemm16(const __half* __restrict__ A, const __half* __restrict__ Bt,
          const float* __restrict__ b0p, const float* __restrict__ b1p,
          const float* __restrict__ b2p, const float* __restrict__ extra,
          float* __restrict__ C, int M, int CS)
{
    extern __shared__ char smem[];
    const uint32_t aBase = smem_u32(smem);
    const uint32_t bBase = aBase + STG * STAGE_BYTES;
    const int tid = threadIdx.x, wid = tid >> 5, lane = tid & 31;
    const int nt = blockIdx.x, mt = blockIdx.y;
    const int warpM = wid & 3, warpN = wid >> 2;

    const int lrow = tid >> 2, lch = tid & 3;
    const __half* ag0 = A + (size_t)(mt * 128 + lrow) * NH + lch * 8;
    const __half* bg0 = Bt + (size_t)(nt * 128 + lrow) * NH + lch * 8;
    const uint32_t sA0 = swz(lrow, lch), sA1 = swz(lrow + 64, lch);

#define LOAD_STAGE(kb, stg) do { \
    const __half* _ag = ag0 + (kb) * 32; \
    const __half* _bg = bg0 + (kb) * 32; \
    uint32_t _da = aBase + (stg) * STAGE_BYTES; \
    uint32_t _db = bBase + (stg) * STAGE_BYTES; \
    CP_ASYNC16(_da + sA0, _ag); \
    CP_ASYNC16(_da + sA1, _ag + (size_t)64 * NH); \
    CP_ASYNC16(_db + sA0, _bg); \
    CP_ASYNC16(_db + sA1, _bg + (size_t)64 * NH); \
    CP_COMMIT(); \
} while (0)

    LOAD_STAGE(0, 0);
    LOAD_STAGE(1, 1);
    LOAD_STAGE(2, 2);

    const int lr = lane & 7;
    const int aRowB = warpM * 32 + lr + ((lane >> 3) & 1) * 8;
    const int aChB  = (lane >> 4);
    const int bRowB = warpN * 64 + lr + (lane >> 4) * 8;
    const int bChB  = (lane >> 3) & 1;

    float acc[64];
#pragma unroll
    for (int i = 0; i < 64; i++) acc[i] = 0.f;

    for (int kb = 0; kb < KBLKS; kb++) {
        const int stg = kb & 3;
        CP_WAIT(2);
        __syncthreads();
        if (kb + 3 < KBLKS) LOAD_STAGE(kb + 3, (kb + 3) & 3);

        const uint32_t da = aBase + stg * STAGE_BYTES;
        const uint32_t db = bBase + stg * STAGE_BYTES;
#pragma unroll
        for (int ks = 0; ks < 2; ks++) {
            uint32_t af[2][4];
#pragma unroll
            for (int mi = 0; mi < 2; mi++)
                ldsm4(af[mi], da + swz(aRowB + mi * 16, ks * 2 + aChB));
#pragma unroll
            for (int p = 0; p < 4; p++) {
                uint32_t bf[4];
                ldsm4(bf, db + swz(bRowB + p * 16, ks * 2 + bChB));
#pragma unroll
                for (int mi = 0; mi < 2; mi++) {
                    mma16816f(&acc[(mi * 8 + 2 * p + 0) * 4], af[mi], bf + 0);
                    mma16816f(&acc[(mi * 8 + 2 * p + 1) * 4], af[mi], bf + 2);
                }
            }
        }
        // trailing __syncthreads removed (see header comment)
    }

#pragma unroll
    for (int mi = 0; mi < 2; mi++) {
#pragma unroll
        for (int ntile = 0; ntile < 8; ntile++) {
            const float* c = &acc[(mi * 8 + ntile) * 4];
            int row0 = mt * 128 + warpM * 32 + mi * 16 + (lane >> 2);
            int col  = nt * 128 + warpN * 64 + ntile * 8 + (lane & 3) * 2;
            int seg = col >> 9;
            const float* bp = (seg == 0) ? b0p : (seg == 1) ? b1p : b2p;
            int cl = col & 511;
            float bb0 = bp[cl], bb1 = bp[cl + 1];
#pragma unroll
            for (int half0 = 0; half0 < 2; half0++) {
                int row = row0 + half0 * 8;
                if (row >= M) continue;
                float2 o;
                o.x = c[half0 * 2 + 0] + bb0;
                o.y = c[half0 * 2 + 1] + bb1;
                if (EPI == 0) {
                    const float* e = extra + (size_t)(row & (NL - 1)) * NH + col;
                    o.x += e[0]; o.y += e[1];
                }
                if (EPI == 2) {
                    o.x = o.x > 0.f ? o.x : 0.2f * o.x;
                    o.y = o.y > 0.f ? o.y : 0.2f * o.y;
                }
                *(float2*)(C + (size_t)row * CS + col) = o;
            }
        }
    }
#undef LOAD_STAGE
}

// ---------------- A conversion: fp32 -> fp16 (for `data` only) --------------
__global__ __launch_bounds__(256) void convA16_k(const float* __restrict__ in,
                                                 __half* __restrict__ out, int n4)
{
    int i = blockIdx.x * 256 + threadIdx.x;
    if (i >= n4) return;
    float4 x = ((const float4*)in)[i];
    ((__half2*)out)[i * 2]     = __floats2half2_rn(x.x, x.y);
    ((__half2*)out)[i * 2 + 1] = __floats2half2_rn(x.z, x.w);
}

// ---------------- ALL weight transposes -> fp16 in ONE launch ---------------
__global__ __launch_bounds__(256) void convB_all_k(
    const float* __restrict__ fc_w, const float* __restrict__ wq,
    const float* __restrict__ wk,   const float* __restrict__ wv,
    const float* __restrict__ wo,   __half* __restrict__ b16)
{
    __shared__ float t[32][33];
    int s = blockIdx.z;
    const float* W;
    __half* Bt;
    if (s == 0) {
        W = fc_w; Bt = b16;
    } else {
        int i = (s - 1) >> 2, j = (s - 1) & 3;
        const float* src = (j == 0) ? wq : (j == 1) ? wk : (j == 2) ? wv : wo;
        W  = src + (size_t)i * NH * NH;
        Bt = b16 + (size_t)(512 + i * 2048 + j * 512) * NH;
    }
    int k0 = blockIdx.x * 32, n0 = blockIdx.y * 32;
    int tx = threadIdx.x & 31, ty = threadIdx.x >> 5;
#pragma unroll
    for (int i = 0; i < 32; i += 8)
        t[ty + i][tx] = W[(size_t)(k0 + ty + i) * NH + n0 + tx];
    __syncthreads();
#pragma unroll
    for (int i = 0; i < 32; i += 8) {
        int n = n0 + ty + i, k = k0 + tx;
        Bt[(size_t)n * NH + k] = __float2half_rn(t[tx][ty + i]);
    }
}

// ---------------- relay mean, two-phase ----------------
__global__ void relay_part_k(const float* __restrict__ embs, float* __restrict__ part)
{
    int b = blockIdx.y, ch = blockIdx.x, j = threadIdx.x;
    const float* p = embs + ((size_t)b * NL + ch * 64) * NH + j;
    float s = 0.f;
#pragma unroll 8
    for (int l = 0; l < 64; l++) s += p[(size_t)l * NH];
    part[((size_t)b * 32 + ch) * NH + j] = s;
}
__global__ void relay_fin_k(const float* __restrict__ part, float* __restrict__ relay)
{
    int b = blockIdx.x, j = threadIdx.x;
    float s = 0.f;
#pragma unroll
    for (int c = 0; c < 32; c++) s += part[((size_t)b * 32 + c) * NH + j];
    relay[b * NH + j] = s * (1.f / NL);
}

// ---------------- LayerNorm + concat relay -> a16 (fp16) --------------------
__global__ __launch_bounds__(256) void ln_concat_k(
    const float* __restrict__ nodes, const float* __restrict__ relay,
    const float* __restrict__ gamma, const float* __restrict__ beta,
    __half* __restrict__ a16)
{
    __shared__ float2 sh[8];
    int row = blockIdx.x;
    int b = row / NLP1, l = row - b * NLP1;
    int tid = threadIdx.x;
    __half2* dst = (__half2*)(a16 + (size_t)row * NH);

    if (l == NL) {
        float2 x = ((const float2*)(relay + b * NH))[tid];
        dst[tid] = __floats2half2_rn(x.x, x.y);
        return;
    }
    float2 x = ((const float2*)(nodes + ((size_t)b * NL + l) * NH))[tid];
    float2 v = make_float2(x.x + x.y, x.x * x.x + x.y * x.y);
    int lane = tid & 31, w = tid >> 5;
#pragma unroll
    for (int o = 16; o; o >>= 1) {
        v.x += __shfl_xor_sync(0xffffffffu, v.x, o);
        v.y += __shfl_xor_sync(0xffffffffu, v.y, o);
    }
    if (lane == 0) sh[w] = v;
    __syncthreads();
    if (tid == 0) {
        float2 t = sh[0];
#pragma unroll
        for (int i = 1; i < 8; i++) { t.x += sh[i].x; t.y += sh[i].y; }
        sh[0] = t;
    }
    __syncthreads();
    float2 t = sh[0];
    float mu = t.x * (1.f / NH);
    float var = t.y * (1.f / NH) - mu * mu;
    float inv = rsqrtf(var + 1e-6f);
    float2 g = ((const float2*)gamma)[tid];
    float2 bb = ((const float2*)beta)[tid];
    float ox = (x.x - mu) * inv * g.x + bb.x;
    float oy = (x.y - mu) * inv * g.y + bb.y;
    dst[tid] = __floats2half2_rn(ox, oy);
}

// ---------------- ring attention (fp32 qkv) -> a16 (fp16) -------------------
__global__ __launch_bounds__(256) void ring_attn_k(
    const float* __restrict__ qkv, __half* __restrict__ a16)
{
    int gw = blockIdx.x * 8 + (threadIdx.x >> 5);
    int lane = threadIdx.x & 31;
    int h = gw & 7;
    int l = (gw >> 3) & (NL - 1);
    int b = gw >> 14;
    size_t rb = (size_t)b * NLP1 * QS + (size_t)h * HDIM + lane * 2;
    float2 qv = *(const float2*)(qkv + rb + (size_t)l * QS);

    const float* kk = qkv + rb + 512;
    const float* vv = qkv + rb + 1024;
    float2 z = make_float2(0.f, 0.f);
    float2 km = (l > 0)      ? *(const float2*)(kk + (size_t)(l - 1) * QS) : z;
    float2 kc =                *(const float2*)(kk + (size_t)l       * QS);
    float2 kp = (l < NL - 1) ? *(const float2*)(kk + (size_t)(l + 1) * QS) : z;
    float2 kr =                *(const float2*)(kk + (size_t)NL      * QS);
    float s0 = qv.x * km.x + qv.y * km.y;
    float s1 = qv.x * kc.x + qv.y * kc.y;
    float s2 = qv.x * kp.x + qv.y * kp.y;
    float s3 = qv.x * kr.x + qv.y * kr.y;
#pragma unroll
    for (int o = 16; o; o >>= 1) {
        s0 += __shfl_xor_sync(0xffffffffu, s0, o);
        s1 += __shfl_xor_sync(0xffffffffu, s1, o);
        s2 += __shfl_xor_sync(0xffffffffu, s2, o);
        s3 += __shfl_xor_sync(0xffffffffu, s3, o);
    }
    const float scale = 0.125f;
    s0 *= scale; s1 *= scale; s2 *= scale; s3 *= scale;
    float m = fmaxf(fmaxf(s0, s1), fmaxf(s2, s3));
    float e0 = __expf(s0 - m), e1 = __expf(s1 - m);
    float e2 = __expf(s2 - m), e3 = __expf(s3 - m);
    float inv = 1.f / (e0 + e1 + e2 + e3);
    float2 vm = (l > 0)      ? *(const float2*)(vv + (size_t)(l - 1) * QS) : z;
    float2 vc =                *(const float2*)(vv + (size_t)l       * QS);
    float2 vp = (l < NL - 1) ? *(const float2*)(vv + (size_t)(l + 1) * QS) : z;
    float2 vr =                *(const float2*)(vv + (size_t)NL      * QS);
    float ox = (e0 * vm.x + e1 * vc.x + e2 * vp.x + e3 * vr.x) * inv;
    float oy = (e0 * vm.y + e1 * vc.y + e2 * vp.y + e3 * vr.y) * inv;

    __half2* dst = (__half2*)(a16 + ((size_t)b * NL + l) * NH + (size_t)h * HDIM);
    dst[lane] = __floats2half2_rn(ox, oy);
}

// ---------------- star attention (fp32 qkv) ----------------
__global__ __launch_bounds__(256) void star_attn_k(
    const float* __restrict__ qkv, float* __restrict__ attr)
{
    __shared__ float sq[HDIM];
    __shared__ float sc[NLP1];
    __shared__ float red[8];
    __shared__ float part[4][HDIM];
    int b = blockIdx.x >> 3, h = blockIdx.x & 7;
    int tid = threadIdx.x;
    size_t hb = (size_t)b * NLP1 * QS + (size_t)h * HDIM;
    if (tid < HDIM) sq[tid] = qkv[hb + (size_t)NL * QS + tid];
    __syncthreads();
    float lmax = -1e30f;
    for (int l = tid; l < NLP1; l += 256) {
        const float4* kp = (const float4*)(qkv + hb + 512 + (size_t)l * QS);
        float d = 0.f;
#pragma unroll
        for (int j = 0; j < HDIM / 4; j++) {
            float4 kk = kp[j];
            d += sq[4 * j + 0] * kk.x + sq[4 * j + 1] * kk.y
               + sq[4 * j + 2] * kk.z + sq[4 * j + 3] * kk.w;
        }
        d *= 0.125f;
        sc[l] = d;
        lmax = fmaxf(lmax, d);
    }
    int lane = tid & 31, w = tid >> 5;
#pragma unroll
    for (int o = 16; o; o >>= 1) lmax = fmaxf(lmax, __shfl_xor_sync(0xffffffffu, lmax, o));
    if (lane == 0) red[w] = lmax;
    __syncthreads();
    if (tid == 0) {
        float m = red[0];
#pragma unroll
        for (int i = 1; i < 8; i++) m = fmaxf(m, red[i]);
        red[0] = m;
    }
    __syncthreads();
    float m = red[0];
    __syncthreads();
    float lsum = 0.f;
    for (int l = tid; l < NLP1; l += 256) {
        float e = __expf(sc[l] - m);
        sc[l] = e;
        lsum += e;
    }
#pragma unroll
    for (int o = 16; o; o >>= 1) lsum += __shfl_xor_sync(0xffffffffu, lsum, o);
    if (lane == 0) red[w] = lsum;
    __syncthreads();
    if (tid == 0) {
        float s = 0.f;
#pragma unroll
        for (int i = 0; i < 8; i++) s += red[i];
        red[0] = s;
    }
    __syncthreads();
    float Zinv = 1.f / red[0];
    int d = tid & 63, g = tid >> 6;
    float acc = 0.f;
    for (int l = g; l < NLP1; l += 4)
        acc += sc[l] * qkv[hb + 1024 + (size_t)l * QS + d];
    part[g][d] = acc;
    __syncthreads();
    if (tid < HDIM)
        attr[(size_t)b * NH + h * HDIM + tid] =
            (part[0][tid] + part[1][tid] + part[2][tid] + part[3][tid]) * Zinv;
}

// ---------------- star output GEMM + leaky (widened: 64 blocks) -------------
__global__ __launch_bounds__(256) void star_out_k(
    const float* __restrict__ attr, const float* __restrict__ w,
    const float* __restrict__ bias, float* __restrict__ relay)
{
    __shared__ float sa[512];
    __shared__ float red[4][64];
    int b = blockIdx.y, cx = blockIdx.x;
    int t = threadIdx.x;
    sa[t]       = attr[b * NH + t];
    sa[t + 256] = attr[b * NH + t + 256];
    __syncthreads();
    int col = cx * 64 + (t & 63), g = t >> 6;
    float acc = 0.f;
    const float* wp = w + (size_t)(g * 128) * NH + col;
#pragma unroll 4
    for (int kk = 0; kk < 128; kk++)
        acc += sa[g * 128 + kk] * wp[(size_t)kk * NH];
    red[g][t & 63] = acc;
    __syncthreads();
    if (t < 64) {
        float a = red[0][t] + red[1][t] + red[2][t] + red[3][t] + bias[cx * 64 + t];
        relay[b * NH + cx * 64 + t] = a > 0.f ? a : 0.2f * a;
    }
}

// ---------------- final max, two-phase ----------------
__global__ void final_part_k(const float* __restrict__ nodes, float* __restrict__ part)
{
    int b = blockIdx.y, ch = blockIdx.x, j = threadIdx.x;
    const float* p = nodes + ((size_t)b * NL + ch * 64) * NH + j;
    float m = -3.4e38f;
#pragma unroll 8
    for (int l = 0; l < 64; l++) m = fmaxf(m, p[(size_t)l * NH]);
    part[((size_t)b * 32 + ch) * NH + j] = m;
}
__global__ void final_fin_k(const float* __restrict__ part,
                            const float* __restrict__ relay, float* __restrict__ out)
{
    int b = blockIdx.x, j = threadIdx.x;
    float m = -3.4e38f;
#pragma unroll
    for (int c = 0; c < 32; c++) m = fmaxf(m, part[((size_t)b * 32 + c) * NH + j]);
    out[b * NH + j] = 0.5f * (relay[b * NH + j] + m);
}

// =====================================================================
//  host launch  (R7 schedule: whole GEMMs on s0, star branch on s2,
//  convB on s2 concurrent with convA on s0)
// =====================================================================
extern "C" void kernel_launch(void* const* d_in, const int* in_sizes, int n_in,
                              void* d_out, int out_size)
{
    const float* data    = (const float*)d_in[0];
    const float* fc_w    = (const float*)d_in[1];
    const float* fc_b    = (const float*)d_in[2];
    const float* pos_emb = (const float*)d_in[3];
    const float* ln_g    = (const float*)d_in[4];
    const float* ln_b    = (const float*)d_in[5];
    const float* wq      = (const float*)d_in[6];
    const float* wk      = (const float*)d_in[7];
    const float* wv      = (const float*)d_in[8];
    const float* bq      = (const float*)d_in[9];
    const float* bk      = (const float*)d_in[10];
    const float* bv      = (const float*)d_in[11];
    const float* ring_wo = (const float*)d_in[12];
    const float* ring_bo = (const float*)d_in[13];
    const float* star_wo = (const float*)d_in[14];
    const float* star_bo = (const float*)d_in[15];
    float* out = (float*)d_out;

    float *nodes, *qkv, *relay, *attr, *part;
    __half *a16, *b16;
    cudaGetSymbolAddress((void**)&nodes, g_nodes);
    cudaGetSymbolAddress((void**)&qkv,   g_qkv);
    cudaGetSymbolAddress((void**)&relay, g_relay);
    cudaGetSymbolAddress((void**)&attr,  g_attr);
    cudaGetSymbolAddress((void**)&part,  g_part);
    cudaGetSymbolAddress((void**)&a16,   g_a16);
    cudaGetSymbolAddress((void**)&b16,   g_b16);

    static bool init_done = false;
    static cudaStream_t s2;
    static cudaEvent_t evFork[NLAYERS], evJoin[NLAYERS], evFork0, evConvB;
    if (!init_done) {
        cudaFuncSetAttribute(mmagemm16<0>, cudaFuncAttributeMaxDynamicSharedMemorySize, SMEM_GEMM);
        cudaFuncSetAttribute(mmagemm16<1>, cudaFuncAttributeMaxDynamicSharedMemorySize, SMEM_GEMM);
        cudaFuncSetAttribute(mmagemm16<2>, cudaFuncAttributeMaxDynamicSharedMemorySize, SMEM_GEMM);
        cudaStreamCreateWithFlags(&s2, cudaStreamNonBlocking);
        for (int i = 0; i < NLAYERS; i++) {
            cudaEventCreateWithFlags(&evFork[i], cudaEventDisableTiming);
            cudaEventCreateWithFlags(&evJoin[i], cudaEventDisableTiming);
        }
        cudaEventCreateWithFlags(&evFork0, cudaEventDisableTiming);
        cudaEventCreateWithFlags(&evConvB, cudaEventDisableTiming);
        init_done = true;
    }
    cudaStream_t s0 = (cudaStream_t)0;

    const int M_nodes = NB * NL;     // 16384
    const int M_xy    = NB * NLP1;   // 16392
    dim3 gN(4, M_nodes / 128);       // (4,128)  N=512
    dim3 gQKV(12, (M_xy + 127) / 128); // (12,129) N=1536

    // ---- fork s2 from origin (graph-capture rule); convB on s2 ∥ convA on s0
    cudaEventRecord(evFork0, s0);
    cudaStreamWaitEvent(s2, evFork0, 0);
    convB_all_k<<<dim3(16, 16, 1 + NLAYERS * 4), 256, 0, s2>>>(fc_w, wq, wk, wv, ring_wo, b16);
    cudaEventRecord(evConvB, s2);
    convA16_k<<<(M_nodes * 128 + 255) / 256, 256>>>(data, a16, M_nodes * 128);
    cudaStreamWaitEvent(s0, evConvB, 0);

    // ---- embeddings ----
    mmagemm16<0><<<gN, 256, SMEM_GEMM>>>(a16, b16, fc_b, fc_b, fc_b, pos_emb,
                                         nodes, M_nodes, NH);
    relay_part_k<<<dim3(32, NB), NH>>>(nodes, part);
    relay_fin_k<<<NB, NH>>>(part, relay);

    for (int i = 0; i < NLAYERS; i++) {
        size_t bOff = (size_t)i * 512;
        __half* slot  = b16 + (size_t)(512 + i * 2048) * NH;
        __half* slotO = slot + (size_t)1536 * NH;

        if (i > 0) cudaStreamWaitEvent(s0, evJoin[i - 1], 0);  // relay ready
        ln_concat_k<<<NB * NLP1, 256>>>(nodes, relay, ln_g + bOff, ln_b + bOff, a16);

        mmagemm16<1><<<gQKV, 256, SMEM_GEMM>>>(a16, slot, bq + bOff, bk + bOff,
                                               bv + bOff, nullptr, qkv, M_xy, QS);

        // fork: star branch on s2 (depends only on qkv), overlaps ring branch
        cudaEventRecord(evFork[i], s0);
        cudaStreamWaitEvent(s2, evFork[i], 0);
        star_attn_k<<<NB * NHEADS, 256, 0, s2>>>(qkv, attr);
        star_out_k<<<dim3(8, NB), 256, 0, s2>>>(attr, star_wo + (size_t)i * 512 * 512,
                                                star_bo + bOff, relay);
        cudaEventRecord(evJoin[i], s2);

        ring_attn_k<<<NB * NL * NHEADS / 8, 256>>>(qkv, a16);
        mmagemm16<2><<<gN, 256, SMEM_GEMM>>>(a16, slotO, ring_bo + bOff, ring_bo + bOff,
                                             ring_bo + bOff, nullptr, nodes, M_nodes, NH);
    }

    final_part_k<<<dim3(32, NB), NH>>>(nodes, part);
    cudaStreamWaitEvent(s0, evJoin[NLAYERS - 1], 0);           // relay ready
    final_fin_k<<<NB, NH>>>(part, relay, out);
}

// round 14
// speedup vs baseline: 1.1161x; 1.0091x over previous
#include <cuda_runtime.h>
#include <cuda_fp16.h>
#include <math.h>
#include <stdint.h>

// ---------------- problem constants ----------------
#define NB 8
#define NL 2048
#define NLP1 2049
#define NH 512
#define NHEADS 8
#define HDIM 64
#define NLAYERS 4

#define MPAD 16512          // 129*128 row capacity (A padding for cp.async)
#define QS 1536             // fused qkv row stride (fp32)

// ---------------- scratch (device globals; no allocation) ----------------
__device__ float g_nodes[(size_t)NB * NL * NH];            // 32 MB
__device__ float g_qkv [(size_t)NB * NLP1 * QS];           // 100 MB (fp32)
__device__ float g_relay[NB * NH];
__device__ float g_attr [NB * NH];
__device__ float g_part [(size_t)NB * 32 * NH];
__device__ __align__(16) __half g_a16[(size_t)MPAD * NH];  // 16.9 MB (GEMM A operand)
__device__ __align__(16) __half g_b16[(size_t)(512 + NLAYERS * 2048) * NH]; // 8.9 MB

// =====================================================================
//  low-level helpers
// =====================================================================
__device__ __forceinline__ uint32_t smem_u32(const void* p) {
    uint32_t a;
    asm("{ .reg .u64 t; cvta.to.shared.u64 t, %1; cvt.u32.u64 %0, t; }"
        : "=r"(a) : "l"(p));
    return a;
}

#define CP_ASYNC16(dst, src) \
    asm volatile("cp.async.cg.shared.global [%0], [%1], 16;" \
        :: "r"(dst), "l"(src) : "memory")
#define CP_COMMIT() asm volatile("cp.async.commit_group;" ::: "memory")
#define CP_WAIT(n)  asm volatile("cp.async.wait_group %0;" :: "n"(n) : "memory")

__device__ __forceinline__ void ldsm4(uint32_t* r, uint32_t addr) {
    asm volatile("ldmatrix.sync.aligned.m8n8.x4.shared.b16 {%0,%1,%2,%3}, [%4];"
        : "=r"(r[0]), "=r"(r[1]), "=r"(r[2]), "=r"(r[3]) : "r"(addr));
}

__device__ __forceinline__ void mma16816f(float* c, const uint32_t* a, const uint32_t* b) {
    asm volatile("mma.sync.aligned.m16n8k16.row.col.f32.f16.f16.f32 "
        "{%0,%1,%2,%3}, {%4,%5,%6,%7}, {%8,%9}, {%0,%1,%2,%3};"
        : "+f"(c[0]), "+f"(c[1]), "+f"(c[2]), "+f"(c[3])
        : "r"(a[0]), "r"(a[1]), "r"(a[2]), "r"(a[3]), "r"(b[0]), "r"(b[1]));
}

// swizzled byte offset within one stage tile: 128 rows x 64B (4 chunks of 16B)
__device__ __forceinline__ uint32_t swz(int row, int chunk) {
    return (uint32_t)(row * 64 + ((chunk ^ ((row >> 1) & 3)) << 4));
}

// =====================================================================
//  fp16 mma.sync GEMM: C[M, CS-cols] = A[M,512] @ Bt[N,512]^T + epilogue
//  tile 128x128, 8 warps (4M x 2N), kblock 32, 4-stage cp.async.
//  Single leading __syncthreads per k-iteration (trailing barrier removed:
//  with 4 stages and wait_group(2), the leading sync at iter kb already
//  orders all reads of stage (kb-1)&3 before the cp.async that overwrites
//  that same physical stage for kb+3).
//  EPI 0: +bias +pos_emb ; 1: +bias ; 2: leaky(+bias)
// =====================================================================
#define STG 4
#define STAGE_BYTES 8192
#define SMEM_GEMM (2 * STG * STAGE_BYTES)
#define KBLKS 16

template<int EPI>
__global__ void __launch_bounds__(256, 2)
mmagemm16(const __half* __restrict__ A, const __half* __restrict__ Bt,
          const float* __restrict__ b0p, const float* __restrict__ b1p,
          const float* __restrict__ b2p, const float* __restrict__ extra,
          float* __restrict__ C, int M, int CS)
{
    extern __shared__ char smem[];
    const uint32_t aBase = smem_u32(smem);
    const uint32_t bBase = aBase + STG * STAGE_BYTES;
    const int tid = threadIdx.x, wid = tid >> 5, lane = tid & 31;
    const int nt = blockIdx.x, mt = blockIdx.y;
    const int warpM = wid & 3, warpN = wid >> 2;

    const int lrow = tid >> 2, lch = tid & 3;
    const __half* ag0 = A + (size_t)(mt * 128 + lrow) * NH + lch * 8;
    const __half* bg0 = Bt + (size_t)(nt * 128 + lrow) * NH + lch * 8;
    const uint32_t sA0 = swz(lrow, lch), sA1 = swz(lrow + 64, lch);

#define LOAD_STAGE(kb, stg) do { \
    const __half* _ag = ag0 + (kb) * 32; \
    const __half* _bg = bg0 + (kb) * 32; \
    uint32_t _da = aBase + (stg) * STAGE_BYTES; \
    uint32_t _db = bBase + (stg) * STAGE_BYTES; \
    CP_ASYNC16(_da + sA0, _ag); \
    CP_ASYNC16(_da + sA1, _ag + (size_t)64 * NH); \
    CP_ASYNC16(_db + sA0, _bg); \
    CP_ASYNC16(_db + sA1, _bg + (size_t)64 * NH); \
    CP_COMMIT(); \
} while (0)

    LOAD_STAGE(0, 0);
    LOAD_STAGE(1, 1);
    LOAD_STAGE(2, 2);

    const int lr = lane & 7;
    const int aRowB = warpM * 32 + lr + ((lane >> 3) & 1) * 8;
    const int aChB  = (lane >> 4);
    const int bRowB = warpN * 64 + lr + (lane >> 4) * 8;
    const int bChB  = (lane >> 3) & 1;

    float acc[64];
#pragma unroll
    for (int i = 0; i < 64; i++) acc[i] = 0.f;

    for (int kb = 0; kb < KBLKS; kb++) {
        const int stg = kb & 3;
        CP_WAIT(2);
        __syncthreads();
        if (kb + 3 < KBLKS) LOAD_STAGE(kb + 3, (kb + 3) & 3);

        const uint32_t da = aBase + stg * STAGE_BYTES;
        const uint32_t db = bBase + stg * STAGE_BYTES;
#pragma unroll
        for (int ks = 0; ks < 2; ks++) {
            uint32_t af[2][4];
#pragma unroll
            for (int mi = 0; mi < 2; mi++)
                ldsm4(af[mi], da + swz(aRowB + mi * 16, ks * 2 + aChB));
#pragma unroll
            for (int p = 0; p < 4; p++) {
                uint32_t bf[4];
                ldsm4(bf, db + swz(bRowB + p * 16, ks * 2 + bChB));
#pragma unroll
                for (int mi = 0; mi < 2; mi++) {
                    mma16816f(&acc[(mi * 8 + 2 * p + 0) * 4], af[mi], bf + 0);
                    mma16816f(&acc[(mi * 8 + 2 * p + 1) * 4], af[mi], bf + 2);
                }
            }
        }
        // trailing __syncthreads removed (see header comment)
    }

#pragma unroll
    for (int mi = 0; mi < 2; mi++) {
#pragma unroll
        for (int ntile = 0; ntile < 8; ntile++) {
            const float* c = &acc[(mi * 8 + ntile) * 4];
            int row0 = mt * 128 + warpM * 32 + mi * 16 + (lane >> 2);
            int col  = nt * 128 + warpN * 64 + ntile * 8 + (lane & 3) * 2;
            int seg = col >> 9;
            const float* bp = (seg == 0) ? b0p : (seg == 1) ? b1p : b2p;
            int cl = col & 511;
            float bb0 = bp[cl], bb1 = bp[cl + 1];
#pragma unroll
            for (int half0 = 0; half0 < 2; half0++) {
                int row = row0 + half0 * 8;
                if (row >= M) continue;
                float2 o;
                o.x = c[half0 * 2 + 0] + bb0;
                o.y = c[half0 * 2 + 1] + bb1;
                if (EPI == 0) {
                    const float* e = extra + (size_t)(row & (NL - 1)) * NH + col;
                    o.x += e[0]; o.y += e[1];
                }
                if (EPI == 2) {
                    o.x = o.x > 0.f ? o.x : 0.2f * o.x;
                    o.y = o.y > 0.f ? o.y : 0.2f * o.y;
                }
                *(float2*)(C + (size_t)row * CS + col) = o;
            }
        }
    }
#undef LOAD_STAGE
}

// ---------------- A conversion: fp32 -> fp16 (for `data` only) --------------
__global__ __launch_bounds__(256) void convA16_k(const float* __restrict__ in,
                                                 __half* __restrict__ out, int n4)
{
    int i = blockIdx.x * 256 + threadIdx.x;
    if (i >= n4) return;
    float4 x = ((const float4*)in)[i];
    ((__half2*)out)[i * 2]     = __floats2half2_rn(x.x, x.y);
    ((__half2*)out)[i * 2 + 1] = __floats2half2_rn(x.z, x.w);
}

// ---------------- ALL weight transposes -> fp16 in ONE launch ---------------
__global__ __launch_bounds__(256) void convB_all_k(
    const float* __restrict__ fc_w, const float* __restrict__ wq,
    const float* __restrict__ wk,   const float* __restrict__ wv,
    const float* __restrict__ wo,   __half* __restrict__ b16)
{
    __shared__ float t[32][33];
    int s = blockIdx.z;
    const float* W;
    __half* Bt;
    if (s == 0) {
        W = fc_w; Bt = b16;
    } else {
        int i = (s - 1) >> 2, j = (s - 1) & 3;
        const float* src = (j == 0) ? wq : (j == 1) ? wk : (j == 2) ? wv : wo;
        W  = src + (size_t)i * NH * NH;
        Bt = b16 + (size_t)(512 + i * 2048 + j * 512) * NH;
    }
    int k0 = blockIdx.x * 32, n0 = blockIdx.y * 32;
    int tx = threadIdx.x & 31, ty = threadIdx.x >> 5;
#pragma unroll
    for (int i = 0; i < 32; i += 8)
        t[ty + i][tx] = W[(size_t)(k0 + ty + i) * NH + n0 + tx];
    __syncthreads();
#pragma unroll
    for (int i = 0; i < 32; i += 8) {
        int n = n0 + ty + i, k = k0 + tx;
        Bt[(size_t)n * NH + k] = __float2half_rn(t[tx][ty + i]);
    }
}

// ---------------- relay mean, two-phase ----------------
__global__ void relay_part_k(const float* __restrict__ embs, float* __restrict__ part)
{
    int b = blockIdx.y, ch = blockIdx.x, j = threadIdx.x;
    const float* p = embs + ((size_t)b * NL + ch * 64) * NH + j;
    float s = 0.f;
#pragma unroll 8
    for (int l = 0; l < 64; l++) s += p[(size_t)l * NH];
    part[((size_t)b * 32 + ch) * NH + j] = s;
}
__global__ void relay_fin_k(const float* __restrict__ part, float* __restrict__ relay)
{
    int b = blockIdx.x, j = threadIdx.x;
    float s = 0.f;
#pragma unroll
    for (int c = 0; c < 32; c++) s += part[((size_t)b * 32 + c) * NH + j];
    relay[b * NH + j] = s * (1.f / NL);
}

// ---------------- LayerNorm + concat relay -> a16 (fp16) --------------------
__global__ __launch_bounds__(256) void ln_concat_k(
    const float* __restrict__ nodes, const float* __restrict__ relay,
    const float* __restrict__ gamma, const float* __restrict__ beta,
    __half* __restrict__ a16)
{
    __shared__ float2 sh[8];
    int row = blockIdx.x;
    int b = row / NLP1, l = row - b * NLP1;
    int tid = threadIdx.x;
    __half2* dst = (__half2*)(a16 + (size_t)row * NH);

    if (l == NL) {
        float2 x = ((const float2*)(relay + b * NH))[tid];
        dst[tid] = __floats2half2_rn(x.x, x.y);
        return;
    }
    float2 x = ((const float2*)(nodes + ((size_t)b * NL + l) * NH))[tid];
    float2 v = make_float2(x.x + x.y, x.x * x.x + x.y * x.y);
    int lane = tid & 31, w = tid >> 5;
#pragma unroll
    for (int o = 16; o; o >>= 1) {
        v.x += __shfl_xor_sync(0xffffffffu, v.x, o);
        v.y += __shfl_xor_sync(0xffffffffu, v.y, o);
    }
    if (lane == 0) sh[w] = v;
    __syncthreads();
    if (tid == 0) {
        float2 t = sh[0];
#pragma unroll
        for (int i = 1; i < 8; i++) { t.x += sh[i].x; t.y += sh[i].y; }
        sh[0] = t;
    }
    __syncthreads();
    float2 t = sh[0];
    float mu = t.x * (1.f / NH);
    float var = t.y * (1.f / NH) - mu * mu;
    float inv = rsqrtf(var + 1e-6f);
    float2 g = ((const float2*)gamma)[tid];
    float2 bb = ((const float2*)beta)[tid];
    float ox = (x.x - mu) * inv * g.x + bb.x;
    float oy = (x.y - mu) * inv * g.y + bb.y;
    dst[tid] = __floats2half2_rn(ox, oy);
}

// ---------------- ring attention (fp32 qkv) -> a16 (fp16) -------------------
// TWO adjacent l per warp: shares the middle k/v row loads (12 float2 loads
// per l-pair instead of 18). Numerics identical per-l to the 1-l version.
__global__ __launch_bounds__(256) void ring_attn_k(
    const float* __restrict__ qkv, __half* __restrict__ a16)
{
    int gw = blockIdx.x * 8 + (threadIdx.x >> 5);   // 0 .. NB*NHEADS*1024-1
    int lane = threadIdx.x & 31;
    int h = gw & 7;
    int l0 = ((gw >> 3) & 1023) * 2;                // even l
    int b = gw >> 13;
    size_t rb = (size_t)b * NLP1 * QS + (size_t)h * HDIM + lane * 2;

    const float* qq = qkv + rb;
    const float* kk = qkv + rb + 512;
    const float* vv = qkv + rb + 1024;
    float2 z = make_float2(0.f, 0.f);

    float2 q0 = *(const float2*)(qq + (size_t)l0 * QS);
    float2 q1 = *(const float2*)(qq + (size_t)(l0 + 1) * QS);

    float2 k0 = (l0 > 0)       ? *(const float2*)(kk + (size_t)(l0 - 1) * QS) : z;
    float2 k1 =                  *(const float2*)(kk + (size_t)l0       * QS);
    float2 k2 =                  *(const float2*)(kk + (size_t)(l0 + 1) * QS);
    float2 k3 = (l0 + 2 < NL)  ? *(const float2*)(kk + (size_t)(l0 + 2) * QS) : z;
    float2 kr =                  *(const float2*)(kk + (size_t)NL       * QS);

    // scores: row l0 uses {k0,k1,k2,kr}; row l0+1 uses {k1,k2,k3,kr}
    float a0 = q0.x * k0.x + q0.y * k0.y;
    float a1 = q0.x * k1.x + q0.y * k1.y;
    float a2 = q0.x * k2.x + q0.y * k2.y;
    float a3 = q0.x * kr.x + q0.y * kr.y;
    float c0 = q1.x * k1.x + q1.y * k1.y;
    float c1 = q1.x * k2.x + q1.y * k2.y;
    float c2 = q1.x * k3.x + q1.y * k3.y;
    float c3 = q1.x * kr.x + q1.y * kr.y;
#pragma unroll
    for (int o = 16; o; o >>= 1) {
        a0 += __shfl_xor_sync(0xffffffffu, a0, o);
        a1 += __shfl_xor_sync(0xffffffffu, a1, o);
        a2 += __shfl_xor_sync(0xffffffffu, a2, o);
        a3 += __shfl_xor_sync(0xffffffffu, a3, o);
        c0 += __shfl_xor_sync(0xffffffffu, c0, o);
        c1 += __shfl_xor_sync(0xffffffffu, c1, o);
        c2 += __shfl_xor_sync(0xffffffffu, c2, o);
        c3 += __shfl_xor_sync(0xffffffffu, c3, o);
    }
    const float scale = 0.125f;
    a0 *= scale; a1 *= scale; a2 *= scale; a3 *= scale;
    c0 *= scale; c1 *= scale; c2 *= scale; c3 *= scale;

    float m0 = fmaxf(fmaxf(a0, a1), fmaxf(a2, a3));
    float e00 = __expf(a0 - m0), e01 = __expf(a1 - m0);
    float e02 = __expf(a2 - m0), e03 = __expf(a3 - m0);
    float inv0 = 1.f / (e00 + e01 + e02 + e03);

    float m1 = fmaxf(fmaxf(c0, c1), fmaxf(c2, c3));
    float e10 = __expf(c0 - m1), e11 = __expf(c1 - m1);
    float e12 = __expf(c2 - m1), e13 = __expf(c3 - m1);
    float inv1 = 1.f / (e10 + e11 + e12 + e13);

    float2 v0 = (l0 > 0)      ? *(const float2*)(vv + (size_t)(l0 - 1) * QS) : z;
    float2 v1 =                 *(const float2*)(vv + (size_t)l0       * QS);
    float2 v2 =                 *(const float2*)(vv + (size_t)(l0 + 1) * QS);
    float2 v3 = (l0 + 2 < NL) ? *(const float2*)(vv + (size_t)(l0 + 2) * QS) : z;
    float2 vr =                 *(const float2*)(vv + (size_t)NL       * QS);

    float ox0 = (e00 * v0.x + e01 * v1.x + e02 * v2.x + e03 * vr.x) * inv0;
    float oy0 = (e00 * v0.y + e01 * v1.y + e02 * v2.y + e03 * vr.y) * inv0;
    float ox1 = (e10 * v1.x + e11 * v2.x + e12 * v3.x + e13 * vr.x) * inv1;
    float oy1 = (e10 * v1.y + e11 * v2.y + e12 * v3.y + e13 * vr.y) * inv1;

    __half2* d0 = (__half2*)(a16 + ((size_t)b * NL + l0) * NH + (size_t)h * HDIM);
    __half2* d1 = (__half2*)(a16 + ((size_t)b * NL + l0 + 1) * NH + (size_t)h * HDIM);
    d0[lane] = __floats2half2_rn(ox0, oy0);
    d1[lane] = __floats2half2_rn(ox1, oy1);
}

// ---------------- star attention (fp32 qkv) ----------------
__global__ __launch_bounds__(256) void star_attn_k(
    const float* __restrict__ qkv, float* __restrict__ attr)
{
    __shared__ float sq[HDIM];
    __shared__ float sc[NLP1];
    __shared__ float red[8];
    __shared__ float part[4][HDIM];
    int b = blockIdx.x >> 3, h = blockIdx.x & 7;
    int tid = threadIdx.x;
    size_t hb = (size_t)b * NLP1 * QS + (size_t)h * HDIM;
    if (tid < HDIM) sq[tid] = qkv[hb + (size_t)NL * QS + tid];
    __syncthreads();
    float lmax = -1e30f;
    for (int l = tid; l < NLP1; l += 256) {
        const float4* kp = (const float4*)(qkv + hb + 512 + (size_t)l * QS);
        float d = 0.f;
#pragma unroll
        for (int j = 0; j < HDIM / 4; j++) {
            float4 kk = kp[j];
            d += sq[4 * j + 0] * kk.x + sq[4 * j + 1] * kk.y
               + sq[4 * j + 2] * kk.z + sq[4 * j + 3] * kk.w;
        }
        d *= 0.125f;
        sc[l] = d;
        lmax = fmaxf(lmax, d);
    }
    int lane = tid & 31, w = tid >> 5;
#pragma unroll
    for (int o = 16; o; o >>= 1) lmax = fmaxf(lmax, __shfl_xor_sync(0xffffffffu, lmax, o));
    if (lane == 0) red[w] = lmax;
    __syncthreads();
    if (tid == 0) {
        float m = red[0];
#pragma unroll
        for (int i = 1; i < 8; i++) m = fmaxf(m, red[i]);
        red[0] = m;
    }
    __syncthreads();
    float m = red[0];
    __syncthreads();
    float lsum = 0.f;
    for (int l = tid; l < NLP1; l += 256) {
        float e = __expf(sc[l] - m);
        sc[l] = e;
        lsum += e;
    }
#pragma unroll
    for (int o = 16; o; o >>= 1) lsum += __shfl_xor_sync(0xffffffffu, lsum, o);
    if (lane == 0) red[w] = lsum;
    __syncthreads();
    if (tid == 0) {
        float s = 0.f;
#pragma unroll
        for (int i = 0; i < 8; i++) s += red[i];
        red[0] = s;
    }
    __syncthreads();
    float Zinv = 1.f / red[0];
    int d = tid & 63, g = tid >> 6;
    float acc = 0.f;
    for (int l = g; l < NLP1; l += 4)
        acc += sc[l] * qkv[hb + 1024 + (size_t)l * QS + d];
    part[g][d] = acc;
    __syncthreads();
    if (tid < HDIM)
        attr[(size_t)b * NH + h * HDIM + tid] =
            (part[0][tid] + part[1][tid] + part[2][tid] + part[3][tid]) * Zinv;
}

// ---------------- star output GEMM + leaky (widened: 64 blocks) -------------
__global__ __launch_bounds__(256) void star_out_k(
    const float* __restrict__ attr, const float* __restrict__ w,
    const float* __restrict__ bias, float* __restrict__ relay)
{
    __shared__ float sa[512];
    __shared__ float red[4][64];
    int b = blockIdx.y, cx = blockIdx.x;
    int t = threadIdx.x;
    sa[t]       = attr[b * NH + t];
    sa[t + 256] = attr[b * NH + t + 256];
    __syncthreads();
    int col = cx * 64 + (t & 63), g = t >> 6;
    float acc = 0.f;
    const float* wp = w + (size_t)(g * 128) * NH + col;
#pragma unroll 4
    for (int kk = 0; kk < 128; kk++)
        acc += sa[g * 128 + kk] * wp[(size_t)kk * NH];
    red[g][t & 63] = acc;
    __syncthreads();
    if (t < 64) {
        float a = red[0][t] + red[1][t] + red[2][t] + red[3][t] + bias[cx * 64 + t];
        relay[b * NH + cx * 64 + t] = a > 0.f ? a : 0.2f * a;
    }
}

// ---------------- final max, two-phase ----------------
__global__ void final_part_k(const float* __restrict__ nodes, float* __restrict__ part)
{
    int b = blockIdx.y, ch = blockIdx.x, j = threadIdx.x;
    const float* p = nodes + ((size_t)b * NL + ch * 64) * NH + j;
    float m = -3.4e38f;
#pragma unroll 8
    for (int l = 0; l < 64; l++) m = fmaxf(m, p[(size_t)l * NH]);
    part[((size_t)b * 32 + ch) * NH + j] = m;
}
__global__ void final_fin_k(const float* __restrict__ part,
                            const float* __restrict__ relay, float* __restrict__ out)
{
    int b = blockIdx.x, j = threadIdx.x;
    float m = -3.4e38f;
#pragma unroll
    for (int c = 0; c < 32; c++) m = fmaxf(m, part[((size_t)b * 32 + c) * NH + j]);
    out[b * NH + j] = 0.5f * (relay[b * NH + j] + m);
}

// =====================================================================
//  host launch  (R13 schedule: whole GEMMs on s0, star branch on s2,
//  convB on s2 concurrent with convA on s0)
// =====================================================================
extern "C" void kernel_launch(void* const* d_in, const int* in_sizes, int n_in,
                              void* d_out, int out_size)
{
    const float* data    = (const float*)d_in[0];
    const float* fc_w    = (const float*)d_in[1];
    const float* fc_b    = (const float*)d_in[2];
    const float* pos_emb = (const float*)d_in[3];
    const float* ln_g    = (const float*)d_in[4];
    const float* ln_b    = (const float*)d_in[5];
    const float* wq      = (const float*)d_in[6];
    const float* wk      = (const float*)d_in[7];
    const float* wv      = (const float*)d_in[8];
    const float* bq      = (const float*)d_in[9];
    const float* bk      = (const float*)d_in[10];
    const float* bv      = (const float*)d_in[11];
    const float* ring_wo = (const float*)d_in[12];
    const float* ring_bo = (const float*)d_in[13];
    const float* star_wo = (const float*)d_in[14];
    const float* star_bo = (const float*)d_in[15];
    float* out = (float*)d_out;

    float *nodes, *qkv, *relay, *attr, *part;
    __half *a16, *b16;
    cudaGetSymbolAddress((void**)&nodes, g_nodes);
    cudaGetSymbolAddress((void**)&qkv,   g_qkv);
    cudaGetSymbolAddress((void**)&relay, g_relay);
    cudaGetSymbolAddress((void**)&attr,  g_attr);
    cudaGetSymbolAddress((void**)&part,  g_part);
    cudaGetSymbolAddress((void**)&a16,   g_a16);
    cudaGetSymbolAddress((void**)&b16,   g_b16);

    static bool init_done = false;
    static cudaStream_t s2;
    static cudaEvent_t evFork[NLAYERS], evJoin[NLAYERS], evFork0, evConvB;
    if (!init_done) {
        cudaFuncSetAttribute(mmagemm16<0>, cudaFuncAttributeMaxDynamicSharedMemorySize, SMEM_GEMM);
        cudaFuncSetAttribute(mmagemm16<1>, cudaFuncAttributeMaxDynamicSharedMemorySize, SMEM_GEMM);
        cudaFuncSetAttribute(mmagemm16<2>, cudaFuncAttributeMaxDynamicSharedMemorySize, SMEM_GEMM);
        cudaStreamCreateWithFlags(&s2, cudaStreamNonBlocking);
        for (int i = 0; i < NLAYERS; i++) {
            cudaEventCreateWithFlags(&evFork[i], cudaEventDisableTiming);
            cudaEventCreateWithFlags(&evJoin[i], cudaEventDisableTiming);
        }
        cudaEventCreateWithFlags(&evFork0, cudaEventDisableTiming);
        cudaEventCreateWithFlags(&evConvB, cudaEventDisableTiming);
        init_done = true;
    }
    cudaStream_t s0 = (cudaStream_t)0;

    const int M_nodes = NB * NL;     // 16384
    const int M_xy    = NB * NLP1;   // 16392
    dim3 gN(4, M_nodes / 128);       // (4,128)  N=512
    dim3 gQKV(12, (M_xy + 127) / 128); // (12,129) N=1536

    // ---- fork s2 from origin (graph-capture rule); convB on s2 ∥ convA on s0
    cudaEventRecord(evFork0, s0);
    cudaStreamWaitEvent(s2, evFork0, 0);
    convB_all_k<<<dim3(16, 16, 1 + NLAYERS * 4), 256, 0, s2>>>(fc_w, wq, wk, wv, ring_wo, b16);
    cudaEventRecord(evConvB, s2);
    convA16_k<<<(M_nodes * 128 + 255) / 256, 256>>>(data, a16, M_nodes * 128);
    cudaStreamWaitEvent(s0, evConvB, 0);

    // ---- embeddings ----
    mmagemm16<0><<<gN, 256, SMEM_GEMM>>>(a16, b16, fc_b, fc_b, fc_b, pos_emb,
                                         nodes, M_nodes, NH);
    relay_part_k<<<dim3(32, NB), NH>>>(nodes, part);
    relay_fin_k<<<NB, NH>>>(part, relay);

    for (int i = 0; i < NLAYERS; i++) {
        size_t bOff = (size_t)i * 512;
        __half* slot  = b16 + (size_t)(512 + i * 2048) * NH;
        __half* slotO = slot + (size_t)1536 * NH;

        if (i > 0) cudaStreamWaitEvent(s0, evJoin[i - 1], 0);  // relay ready
        ln_concat_k<<<NB * NLP1, 256>>>(nodes, relay, ln_g + bOff, ln_b + bOff, a16);

        mmagemm16<1><<<gQKV, 256, SMEM_GEMM>>>(a16, slot, bq + bOff, bk + bOff,
                                               bv + bOff, nullptr, qkv, M_xy, QS);

        // fork: star branch on s2 (depends only on qkv), overlaps ring branch
        cudaEventRecord(evFork[i], s0);
        cudaStreamWaitEvent(s2, evFork[i], 0);
        star_attn_k<<<NB * NHEADS, 256, 0, s2>>>(qkv, attr);
        star_out_k<<<dim3(8, NB), 256, 0, s2>>>(attr, star_wo + (size_t)i * 512 * 512,
                                                star_bo + bOff, relay);
        cudaEventRecord(evJoin[i], s2);

        // 2-l-per-warp ring attention: NB*NHEADS*1024 warps / 8 per block
        ring_attn_k<<<NB * NHEADS * 1024 / 8, 256>>>(qkv, a16);
        mmagemm16<2><<<gN, 256, SMEM_GEMM>>>(a16, slotO, ring_bo + bOff, ring_bo + bOff,
                                             ring_bo + bOff, nullptr, nodes, M_nodes, NH);
    }

    final_part_k<<<dim3(32, NB), NH>>>(nodes, part);
    cudaStreamWaitEvent(s0, evJoin[NLAYERS - 1], 0);           // relay ready
    final_fin_k<<<NB, NH>>>(part, relay, out);
}

// round 15
// speedup vs baseline: 1.1226x; 1.0058x over previous
#include <cuda_runtime.h>
#include <cuda_fp16.h>
#include <math.h>
#include <stdint.h>

// ---------------- problem constants ----------------
#define NB 8
#define NL 2048
#define NLP1 2049
#define NH 512
#define NHEADS 8
#define HDIM 64
#define NLAYERS 4

#define MPAD 16512          // 129*128 row capacity (A padding for cp.async)
#define QS 1536             // fused qkv row stride (fp32)

// ---------------- scratch (device globals; no allocation) ----------------
__device__ float g_nodes[(size_t)NB * NL * NH];            // 32 MB
__device__ float g_qkv [(size_t)NB * NLP1 * QS];           // 100 MB (fp32)
__device__ float g_relay[NB * NH];
__device__ float g_attr [NB * NH];
__device__ float g_part [(size_t)2 * 128 * NH];            // tile partials: sum | max
__device__ __align__(16) __half g_a16[(size_t)MPAD * NH];  // 16.9 MB (GEMM A operand)
__device__ __align__(16) __half g_b16[(size_t)(512 + NLAYERS * 2048) * NH]; // 8.9 MB

// =====================================================================
//  low-level helpers
// =====================================================================
__device__ __forceinline__ uint32_t smem_u32(const void* p) {
    uint32_t a;
    asm("{ .reg .u64 t; cvta.to.shared.u64 t, %1; cvt.u32.u64 %0, t; }"
        : "=r"(a) : "l"(p));
    return a;
}

#define CP_ASYNC16(dst, src) \
    asm volatile("cp.async.cg.shared.global [%0], [%1], 16;" \
        :: "r"(dst), "l"(src) : "memory")
#define CP_COMMIT() asm volatile("cp.async.commit_group;" ::: "memory")
#define CP_WAIT(n)  asm volatile("cp.async.wait_group %0;" :: "n"(n) : "memory")

__device__ __forceinline__ void ldsm4(uint32_t* r, uint32_t addr) {
    asm volatile("ldmatrix.sync.aligned.m8n8.x4.shared.b16 {%0,%1,%2,%3}, [%4];"
        : "=r"(r[0]), "=r"(r[1]), "=r"(r[2]), "=r"(r[3]) : "r"(addr));
}

__device__ __forceinline__ void mma16816f(float* c, const uint32_t* a, const uint32_t* b) {
    asm volatile("mma.sync.aligned.m16n8k16.row.col.f32.f16.f16.f32 "
        "{%0,%1,%2,%3}, {%4,%5,%6,%7}, {%8,%9}, {%0,%1,%2,%3};"
        : "+f"(c[0]), "+f"(c[1]), "+f"(c[2]), "+f"(c[3])
        : "r"(a[0]), "r"(a[1]), "r"(a[2]), "r"(a[3]), "r"(b[0]), "r"(b[1]));
}

// swizzled byte offset within one stage tile: 128 rows x 64B (4 chunks of 16B)
__device__ __forceinline__ uint32_t swz(int row, int chunk) {
    return (uint32_t)(row * 64 + ((chunk ^ ((row >> 1) & 3)) << 4));
}

// =====================================================================
//  fp16 mma.sync GEMM: C[M, CS-cols] = A[M,512] @ Bt[N,512]^T + epilogue
//  tile 128x128, 8 warps (4M x 2N), kblock 32, 4-stage cp.async.
//  EPI 0: +bias +pos_emb ; 1: +bias ; 2: leaky(+bias)
//  RED 0: none ; 1: per-tile column SUM -> redp ; 2: per-tile column MAX
//  (RED path: tile rows never cross a batch; partials at redp[mt*512+col])
// =====================================================================
#define STG 4
#define STAGE_BYTES 8192
#define SMEM_GEMM (2 * STG * STAGE_BYTES)
#define KBLKS 16

template<int EPI, int RED>
__global__ void __launch_bounds__(256, 2)
mmagemm16(const __half* __restrict__ A, const __half* __restrict__ Bt,
          const float* __restrict__ b0p, const float* __restrict__ b1p,
          const float* __restrict__ b2p, const float* __restrict__ extra,
          float* __restrict__ C, int M, int CS, float* __restrict__ redp)
{
    extern __shared__ char smem[];
    const uint32_t aBase = smem_u32(smem);
    const uint32_t bBase = aBase + STG * STAGE_BYTES;
    const int tid = threadIdx.x, wid = tid >> 5, lane = tid & 31;
    const int nt = blockIdx.x, mt = blockIdx.y;
    const int warpM = wid & 3, warpN = wid >> 2;

    const int lrow = tid >> 2, lch = tid & 3;
    const __half* ag0 = A + (size_t)(mt * 128 + lrow) * NH + lch * 8;
    const __half* bg0 = Bt + (size_t)(nt * 128 + lrow) * NH + lch * 8;
    const uint32_t sA0 = swz(lrow, lch), sA1 = swz(lrow + 64, lch);

#define LOAD_STAGE(kb, stg) do { \
    const __half* _ag = ag0 + (kb) * 32; \
    const __half* _bg = bg0 + (kb) * 32; \
    uint32_t _da = aBase + (stg) * STAGE_BYTES; \
    uint32_t _db = bBase + (stg) * STAGE_BYTES; \
    CP_ASYNC16(_da + sA0, _ag); \
    CP_ASYNC16(_da + sA1, _ag + (size_t)64 * NH); \
    CP_ASYNC16(_db + sA0, _bg); \
    CP_ASYNC16(_db + sA1, _bg + (size_t)64 * NH); \
    CP_COMMIT(); \
} while (0)

    LOAD_STAGE(0, 0);
    LOAD_STAGE(1, 1);
    LOAD_STAGE(2, 2);

    const int lr = lane & 7;
    const int aRowB = warpM * 32 + lr + ((lane >> 3) & 1) * 8;
    const int aChB  = (lane >> 4);
    const int bRowB = warpN * 64 + lr + (lane >> 4) * 8;
    const int bChB  = (lane >> 3) & 1;

    float acc[64];
#pragma unroll
    for (int i = 0; i < 64; i++) acc[i] = 0.f;

    for (int kb = 0; kb < KBLKS; kb++) {
        const int stg = kb & 3;
        CP_WAIT(2);
        __syncthreads();
        if (kb + 3 < KBLKS) LOAD_STAGE(kb + 3, (kb + 3) & 3);

        const uint32_t da = aBase + stg * STAGE_BYTES;
        const uint32_t db = bBase + stg * STAGE_BYTES;
#pragma unroll
        for (int ks = 0; ks < 2; ks++) {
            uint32_t af[2][4];
#pragma unroll
            for (int mi = 0; mi < 2; mi++)
                ldsm4(af[mi], da + swz(aRowB + mi * 16, ks * 2 + aChB));
#pragma unroll
            for (int p = 0; p < 4; p++) {
                uint32_t bf[4];
                ldsm4(bf, db + swz(bRowB + p * 16, ks * 2 + bChB));
#pragma unroll
                for (int mi = 0; mi < 2; mi++) {
                    mma16816f(&acc[(mi * 8 + 2 * p + 0) * 4], af[mi], bf + 0);
                    mma16816f(&acc[(mi * 8 + 2 * p + 1) * 4], af[mi], bf + 2);
                }
            }
        }
    }

    float r0[8], r1[8];
    if (RED) {
#pragma unroll
        for (int i = 0; i < 8; i++) {
            r0[i] = (RED == 1) ? 0.f : -3.4e38f;
            r1[i] = (RED == 1) ? 0.f : -3.4e38f;
        }
    }

#pragma unroll
    for (int mi = 0; mi < 2; mi++) {
#pragma unroll
        for (int ntile = 0; ntile < 8; ntile++) {
            const float* c = &acc[(mi * 8 + ntile) * 4];
            int row0 = mt * 128 + warpM * 32 + mi * 16 + (lane >> 2);
            int col  = nt * 128 + warpN * 64 + ntile * 8 + (lane & 3) * 2;
            int seg = col >> 9;
            const float* bp = (seg == 0) ? b0p : (seg == 1) ? b1p : b2p;
            int cl = col & 511;
            float bb0 = bp[cl], bb1 = bp[cl + 1];
#pragma unroll
            for (int half0 = 0; half0 < 2; half0++) {
                int row = row0 + half0 * 8;
                if (row >= M) continue;
                float2 o;
                o.x = c[half0 * 2 + 0] + bb0;
                o.y = c[half0 * 2 + 1] + bb1;
                if (EPI == 0) {
                    const float* e = extra + (size_t)(row & (NL - 1)) * NH + col;
                    o.x += e[0]; o.y += e[1];
                }
                if (EPI == 2) {
                    o.x = o.x > 0.f ? o.x : 0.2f * o.x;
                    o.y = o.y > 0.f ? o.y : 0.2f * o.y;
                }
                if (RED == 1) { r0[ntile] += o.x; r1[ntile] += o.y; }
                if (RED == 2) { r0[ntile] = fmaxf(r0[ntile], o.x);
                                r1[ntile] = fmaxf(r1[ntile], o.y); }
                *(float2*)(C + (size_t)row * CS + col) = o;
            }
        }
    }

    if (RED) {
        // butterfly over the 8 row-lanes (lane>>2) -> per-warp column partials
#pragma unroll
        for (int o = 4; o <= 16; o <<= 1) {
#pragma unroll
            for (int i = 0; i < 8; i++) {
                float t0 = __shfl_xor_sync(0xffffffffu, r0[i], o);
                float t1 = __shfl_xor_sync(0xffffffffu, r1[i], o);
                if (RED == 1) { r0[i] += t0; r1[i] += t1; }
                else          { r0[i] = fmaxf(r0[i], t0); r1[i] = fmaxf(r1[i], t1); }
            }
        }
        CP_WAIT(0);
        __syncthreads();                         // stages idle; reuse as redbuf
        float* redbuf = (float*)smem;            // [4][128]
        if (lane < 4) {
#pragma unroll
            for (int i = 0; i < 8; i++) {
                int cl = warpN * 64 + i * 8 + lane * 2;
                redbuf[warpM * 128 + cl]     = r0[i];
                redbuf[warpM * 128 + cl + 1] = r1[i];
            }
        }
        __syncthreads();
        if (tid < 128) {
            float v;
            if (RED == 1)
                v = redbuf[tid] + redbuf[128 + tid] + redbuf[256 + tid] + redbuf[384 + tid];
            else
                v = fmaxf(fmaxf(redbuf[tid], redbuf[128 + tid]),
                          fmaxf(redbuf[256 + tid], redbuf[384 + tid]));
            redp[(size_t)mt * NH + nt * 128 + tid] = v;
        }
    }
#undef LOAD_STAGE
}

// ---------------- A conversion: fp32 -> fp16 (for `data` only) --------------
__global__ __launch_bounds__(256) void convA16_k(const float* __restrict__ in,
                                                 __half* __restrict__ out, int n4)
{
    int i = blockIdx.x * 256 + threadIdx.x;
    if (i >= n4) return;
    float4 x = ((const float4*)in)[i];
    ((__half2*)out)[i * 2]     = __floats2half2_rn(x.x, x.y);
    ((__half2*)out)[i * 2 + 1] = __floats2half2_rn(x.z, x.w);
}

// ---------------- ALL weight transposes -> fp16 in ONE launch ---------------
__global__ __launch_bounds__(256) void convB_all_k(
    const float* __restrict__ fc_w, const float* __restrict__ wq,
    const float* __restrict__ wk,   const float* __restrict__ wv,
    const float* __restrict__ wo,   __half* __restrict__ b16)
{
    __shared__ float t[32][33];
    int s = blockIdx.z;
    const float* W;
    __half* Bt;
    if (s == 0) {
        W = fc_w; Bt = b16;
    } else {
        int i = (s - 1) >> 2, j = (s - 1) & 3;
        const float* src = (j == 0) ? wq : (j == 1) ? wk : (j == 2) ? wv : wo;
        W  = src + (size_t)i * NH * NH;
        Bt = b16 + (size_t)(512 + i * 2048 + j * 512) * NH;
    }
    int k0 = blockIdx.x * 32, n0 = blockIdx.y * 32;
    int tx = threadIdx.x & 31, ty = threadIdx.x >> 5;
#pragma unroll
    for (int i = 0; i < 32; i += 8)
        t[ty + i][tx] = W[(size_t)(k0 + ty + i) * NH + n0 + tx];
    __syncthreads();
#pragma unroll
    for (int i = 0; i < 32; i += 8) {
        int n = n0 + ty + i, k = k0 + tx;
        Bt[(size_t)n * NH + k] = __float2half_rn(t[tx][ty + i]);
    }
}

// ---------------- relay from tile partials (16 tiles per batch) -------------
__global__ void relay_fin2_k(const float* __restrict__ part, float* __restrict__ relay)
{
    int b = blockIdx.x, j = threadIdx.x;   // 512 threads
    float s = 0.f;
#pragma unroll
    for (int t = 0; t < 16; t++) s += part[(size_t)(b * 16 + t) * NH + j];
    relay[b * NH + j] = s * (1.f / NL);
}

// ---------------- LayerNorm + concat relay -> a16 (fp16) --------------------
__global__ __launch_bounds__(256) void ln_concat_k(
    const float* __restrict__ nodes, const float* __restrict__ relay,
    const float* __restrict__ gamma, const float* __restrict__ beta,
    __half* __restrict__ a16)
{
    __shared__ float2 sh[8];
    int row = blockIdx.x;
    int b = row / NLP1, l = row - b * NLP1;
    int tid = threadIdx.x;
    __half2* dst = (__half2*)(a16 + (size_t)row * NH);

    if (l == NL) {
        float2 x = ((const float2*)(relay + b * NH))[tid];
        dst[tid] = __floats2half2_rn(x.x, x.y);
        return;
    }
    float2 x = ((const float2*)(nodes + ((size_t)b * NL + l) * NH))[tid];
    float2 v = make_float2(x.x + x.y, x.x * x.x + x.y * x.y);
    int lane = tid & 31, w = tid >> 5;
#pragma unroll
    for (int o = 16; o; o >>= 1) {
        v.x += __shfl_xor_sync(0xffffffffu, v.x, o);
        v.y += __shfl_xor_sync(0xffffffffu, v.y, o);
    }
    if (lane == 0) sh[w] = v;
    __syncthreads();
    if (tid == 0) {
        float2 t = sh[0];
#pragma unroll
        for (int i = 1; i < 8; i++) { t.x += sh[i].x; t.y += sh[i].y; }
        sh[0] = t;
    }
    __syncthreads();
    float2 t = sh[0];
    float mu = t.x * (1.f / NH);
    float var = t.y * (1.f / NH) - mu * mu;
    float inv = rsqrtf(var + 1e-6f);
    float2 g = ((const float2*)gamma)[tid];
    float2 bb = ((const float2*)beta)[tid];
    float ox = (x.x - mu) * inv * g.x + bb.x;
    float oy = (x.y - mu) * inv * g.y + bb.y;
    dst[tid] = __floats2half2_rn(ox, oy);
}

// ---------------- ring attention (fp32 qkv) -> a16 (fp16), 2 l per warp -----
__global__ __launch_bounds__(256) void ring_attn_k(
    const float* __restrict__ qkv, __half* __restrict__ a16)
{
    int gw = blockIdx.x * 8 + (threadIdx.x >> 5);
    int lane = threadIdx.x & 31;
    int h = gw & 7;
    int l0 = ((gw >> 3) & 1023) * 2;
    int b = gw >> 13;
    size_t rb = (size_t)b * NLP1 * QS + (size_t)h * HDIM + lane * 2;

    const float* qq = qkv + rb;
    const float* kk = qkv + rb + 512;
    const float* vv = qkv + rb + 1024;
    float2 z = make_float2(0.f, 0.f);

    float2 q0 = *(const float2*)(qq + (size_t)l0 * QS);
    float2 q1 = *(const float2*)(qq + (size_t)(l0 + 1) * QS);

    float2 k0 = (l0 > 0)      ? *(const float2*)(kk + (size_t)(l0 - 1) * QS) : z;
    float2 k1 =                 *(const float2*)(kk + (size_t)l0       * QS);
    float2 k2 =                 *(const float2*)(kk + (size_t)(l0 + 1) * QS);
    float2 k3 = (l0 + 2 < NL) ? *(const float2*)(kk + (size_t)(l0 + 2) * QS) : z;
    float2 kr =                 *(const float2*)(kk + (size_t)NL       * QS);

    float a0 = q0.x * k0.x + q0.y * k0.y;
    float a1 = q0.x * k1.x + q0.y * k1.y;
    float a2 = q0.x * k2.x + q0.y * k2.y;
    float a3 = q0.x * kr.x + q0.y * kr.y;
    float c0 = q1.x * k1.x + q1.y * k1.y;
    float c1 = q1.x * k2.x + q1.y * k2.y;
    float c2 = q1.x * k3.x + q1.y * k3.y;
    float c3 = q1.x * kr.x + q1.y * kr.y;
#pragma unroll
    for (int o = 16; o; o >>= 1) {
        a0 += __shfl_xor_sync(0xffffffffu, a0, o);
        a1 += __shfl_xor_sync(0xffffffffu, a1, o);
        a2 += __shfl_xor_sync(0xffffffffu, a2, o);
        a3 += __shfl_xor_sync(0xffffffffu, a3, o);
        c0 += __shfl_xor_sync(0xffffffffu, c0, o);
        c1 += __shfl_xor_sync(0xffffffffu, c1, o);
        c2 += __shfl_xor_sync(0xffffffffu, c2, o);
        c3 += __shfl_xor_sync(0xffffffffu, c3, o);
    }
    const float scale = 0.125f;
    a0 *= scale; a1 *= scale; a2 *= scale; a3 *= scale;
    c0 *= scale; c1 *= scale; c2 *= scale; c3 *= scale;

    float m0 = fmaxf(fmaxf(a0, a1), fmaxf(a2, a3));
    float e00 = __expf(a0 - m0), e01 = __expf(a1 - m0);
    float e02 = __expf(a2 - m0), e03 = __expf(a3 - m0);
    float inv0 = 1.f / (e00 + e01 + e02 + e03);

    float m1 = fmaxf(fmaxf(c0, c1), fmaxf(c2, c3));
    float e10 = __expf(c0 - m1), e11 = __expf(c1 - m1);
    float e12 = __expf(c2 - m1), e13 = __expf(c3 - m1);
    float inv1 = 1.f / (e10 + e11 + e12 + e13);

    float2 v0 = (l0 > 0)      ? *(const float2*)(vv + (size_t)(l0 - 1) * QS) : z;
    float2 v1 =                 *(const float2*)(vv + (size_t)l0       * QS);
    float2 v2 =                 *(const float2*)(vv + (size_t)(l0 + 1) * QS);
    float2 v3 = (l0 + 2 < NL) ? *(const float2*)(vv + (size_t)(l0 + 2) * QS) : z;
    float2 vr =                 *(const float2*)(vv + (size_t)NL       * QS);

    float ox0 = (e00 * v0.x + e01 * v1.x + e02 * v2.x + e03 * vr.x) * inv0;
    float oy0 = (e00 * v0.y + e01 * v1.y + e02 * v2.y + e03 * vr.y) * inv0;
    float ox1 = (e10 * v1.x + e11 * v2.x + e12 * v3.x + e13 * vr.x) * inv1;
    float oy1 = (e10 * v1.y + e11 * v2.y + e12 * v3.y + e13 * vr.y) * inv1;

    __half2* d0 = (__half2*)(a16 + ((size_t)b * NL + l0) * NH + (size_t)h * HDIM);
    __half2* d1 = (__half2*)(a16 + ((size_t)b * NL + l0 + 1) * NH + (size_t)h * HDIM);
    d0[lane] = __floats2half2_rn(ox0, oy0);
    d1[lane] = __floats2half2_rn(ox1, oy1);
}

// ---------------- star attention (fp32 qkv) ----------------
__global__ __launch_bounds__(256) void star_attn_k(
    const float* __restrict__ qkv, float* __restrict__ attr)
{
    __shared__ float sq[HDIM];
    __shared__ float sc[NLP1];
    __shared__ float red[8];
    __shared__ float part[4][HDIM];
    int b = blockIdx.x >> 3, h = blockIdx.x & 7;
    int tid = threadIdx.x;
    size_t hb = (size_t)b * NLP1 * QS + (size_t)h * HDIM;
    if (tid < HDIM) sq[tid] = qkv[hb + (size_t)NL * QS + tid];
    __syncthreads();
    float lmax = -1e30f;
    for (int l = tid; l < NLP1; l += 256) {
        const float4* kp = (const float4*)(qkv + hb + 512 + (size_t)l * QS);
        float d = 0.f;
#pragma unroll
        for (int j = 0; j < HDIM / 4; j++) {
            float4 kk = kp[j];
            d += sq[4 * j + 0] * kk.x + sq[4 * j + 1] * kk.y
               + sq[4 * j + 2] * kk.z + sq[4 * j + 3] * kk.w;
        }
        d *= 0.125f;
        sc[l] = d;
        lmax = fmaxf(lmax, d);
    }
    int lane = tid & 31, w = tid >> 5;
#pragma unroll
    for (int o = 16; o; o >>= 1) lmax = fmaxf(lmax, __shfl_xor_sync(0xffffffffu, lmax, o));
    if (lane == 0) red[w] = lmax;
    __syncthreads();
    if (tid == 0) {
        float m = red[0];
#pragma unroll
        for (int i = 1; i < 8; i++) m = fmaxf(m, red[i]);
        red[0] = m;
    }
    __syncthreads();
    float m = red[0];
    __syncthreads();
    float lsum = 0.f;
    for (int l = tid; l < NLP1; l += 256) {
        float e = __expf(sc[l] - m);
        sc[l] = e;
        lsum += e;
    }
#pragma unroll
    for (int o = 16; o; o >>= 1) lsum += __shfl_xor_sync(0xffffffffu, lsum, o);
    if (lane == 0) red[w] = lsum;
    __syncthreads();
    if (tid == 0) {
        float s = 0.f;
#pragma unroll
        for (int i = 0; i < 8; i++) s += red[i];
        red[0] = s;
    }
    __syncthreads();
    float Zinv = 1.f / red[0];
    int d = tid & 63, g = tid >> 6;
    float acc = 0.f;
    for (int l = g; l < NLP1; l += 4)
        acc += sc[l] * qkv[hb + 1024 + (size_t)l * QS + d];
    part[g][d] = acc;
    __syncthreads();
    if (tid < HDIM)
        attr[(size_t)b * NH + h * HDIM + tid] =
            (part[0][tid] + part[1][tid] + part[2][tid] + part[3][tid]) * Zinv;
}

// ---------------- star output GEMM + leaky ----------------
__global__ __launch_bounds__(256) void star_out_k(
    const float* __restrict__ attr, const float* __restrict__ w,
    const float* __restrict__ bias, float* __restrict__ relay)
{
    __shared__ float sa[512];
    __shared__ float red[4][64];
    int b = blockIdx.y, cx = blockIdx.x;
    int t = threadIdx.x;
    sa[t]       = attr[b * NH + t];
    sa[t + 256] = attr[b * NH + t + 256];
    __syncthreads();
    int col = cx * 64 + (t & 63), g = t >> 6;
    float acc = 0.f;
    const float* wp = w + (size_t)(g * 128) * NH + col;
#pragma unroll 4
    for (int kk = 0; kk < 128; kk++)
        acc += sa[g * 128 + kk] * wp[(size_t)kk * NH];
    red[g][t & 63] = acc;
    __syncthreads();
    if (t < 64) {
        float a = red[0][t] + red[1][t] + red[2][t] + red[3][t] + bias[cx * 64 + t];
        relay[b * NH + cx * 64 + t] = a > 0.f ? a : 0.2f * a;
    }
}

// ---------------- final from tile partials + relay ----------------
__global__ void final_fin2_k(const float* __restrict__ partmax,
                             const float* __restrict__ relay, float* __restrict__ out)
{
    int b = blockIdx.x, j = threadIdx.x;   // 512 threads
    float m = -3.4e38f;
#pragma unroll
    for (int t = 0; t < 16; t++) m = fmaxf(m, partmax[(size_t)(b * 16 + t) * NH + j]);
    out[b * NH + j] = 0.5f * (relay[b * NH + j] + m);
}

// =====================================================================
//  host launch
// =====================================================================
extern "C" void kernel_launch(void* const* d_in, const int* in_sizes, int n_in,
                              void* d_out, int out_size)
{
    const float* data    = (const float*)d_in[0];
    const float* fc_w    = (const float*)d_in[1];
    const float* fc_b    = (const float*)d_in[2];
    const float* pos_emb = (const float*)d_in[3];
    const float* ln_g    = (const float*)d_in[4];
    const float* ln_b    = (const float*)d_in[5];
    const float* wq      = (const float*)d_in[6];
    const float* wk      = (const float*)d_in[7];
    const float* wv      = (const float*)d_in[8];
    const float* bq      = (const float*)d_in[9];
    const float* bk      = (const float*)d_in[10];
    const float* bv      = (const float*)d_in[11];
    const float* ring_wo = (const float*)d_in[12];
    const float* ring_bo = (const float*)d_in[13];
    const float* star_wo = (const float*)d_in[14];
    const float* star_bo = (const float*)d_in[15];
    float* out = (float*)d_out;

    float *nodes, *qkv, *relay, *attr, *part;
    __half *a16, *b16;
    cudaGetSymbolAddress((void**)&nodes, g_nodes);
    cudaGetSymbolAddress((void**)&qkv,   g_qkv);
    cudaGetSymbolAddress((void**)&relay, g_relay);
    cudaGetSymbolAddress((void**)&attr,  g_attr);
    cudaGetSymbolAddress((void**)&part,  g_part);
    cudaGetSymbolAddress((void**)&a16,   g_a16);
    cudaGetSymbolAddress((void**)&b16,   g_b16);
    float* partSum = part;
    float* partMax = part + (size_t)128 * NH;

    static bool init_done = false;
    static cudaStream_t s2;
    static cudaEvent_t evFork[NLAYERS], evJoin[NLAYERS], evFork0, evConvB;
    if (!init_done) {
        cudaFuncSetAttribute(mmagemm16<0,1>, cudaFuncAttributeMaxDynamicSharedMemorySize, SMEM_GEMM);
        cudaFuncSetAttribute(mmagemm16<1,0>, cudaFuncAttributeMaxDynamicSharedMemorySize, SMEM_GEMM);
        cudaFuncSetAttribute(mmagemm16<2,0>, cudaFuncAttributeMaxDynamicSharedMemorySize, SMEM_GEMM);
        cudaFuncSetAttribute(mmagemm16<2,2>, cudaFuncAttributeMaxDynamicSharedMemorySize, SMEM_GEMM);
        cudaStreamCreateWithFlags(&s2, cudaStreamNonBlocking);
        for (int i = 0; i < NLAYERS; i++) {
            cudaEventCreateWithFlags(&evFork[i], cudaEventDisableTiming);
            cudaEventCreateWithFlags(&evJoin[i], cudaEventDisableTiming);
        }
        cudaEventCreateWithFlags(&evFork0, cudaEventDisableTiming);
        cudaEventCreateWithFlags(&evConvB, cudaEventDisableTiming);
        init_done = true;
    }
    cudaStream_t s0 = (cudaStream_t)0;

    const int M_nodes = NB * NL;     // 16384
    const int M_xy    = NB * NLP1;   // 16392
    dim3 gN(4, M_nodes / 128);       // (4,128)  N=512
    dim3 gQKV(12, (M_xy + 127) / 128); // (12,129) N=1536

    // ---- fork s2 from origin (graph-capture rule); convB on s2 ∥ convA on s0
    cudaEventRecord(evFork0, s0);
    cudaStreamWaitEvent(s2, evFork0, 0);
    convB_all_k<<<dim3(16, 16, 1 + NLAYERS * 4), 256, 0, s2>>>(fc_w, wq, wk, wv, ring_wo, b16);
    cudaEventRecord(evConvB, s2);
    convA16_k<<<(M_nodes * 128 + 255) / 256, 256>>>(data, a16, M_nodes * 128);
    cudaStreamWaitEvent(s0, evConvB, 0);

    // ---- embeddings: GEMM with fused per-tile column sums -> relay ----
    mmagemm16<0,1><<<gN, 256, SMEM_GEMM>>>(a16, b16, fc_b, fc_b, fc_b, pos_emb,
                                           nodes, M_nodes, NH, partSum);
    relay_fin2_k<<<NB, NH>>>(partSum, relay);

    for (int i = 0; i < NLAYERS; i++) {
        size_t bOff = (size_t)i * 512;
        __half* slot  = b16 + (size_t)(512 + i * 2048) * NH;
        __half* slotO = slot + (size_t)1536 * NH;

        if (i > 0) cudaStreamWaitEvent(s0, evJoin[i - 1], 0);  // relay ready
        ln_concat_k<<<NB * NLP1, 256>>>(nodes, relay, ln_g + bOff, ln_b + bOff, a16);

        mmagemm16<1,0><<<gQKV, 256, SMEM_GEMM>>>(a16, slot, bq + bOff, bk + bOff,
                                                 bv + bOff, nullptr, qkv, M_xy, QS, nullptr);

        // fork: star branch on s2 (depends only on qkv), overlaps ring branch
        cudaEventRecord(evFork[i], s0);
        cudaStreamWaitEvent(s2, evFork[i], 0);
        star_attn_k<<<NB * NHEADS, 256, 0, s2>>>(qkv, attr);
        star_out_k<<<dim3(8, NB), 256, 0, s2>>>(attr, star_wo + (size_t)i * 512 * 512,
                                                star_bo + bOff, relay);
        cudaEventRecord(evJoin[i], s2);

        ring_attn_k<<<NB * NHEADS * 1024 / 8, 256>>>(qkv, a16);
        if (i < NLAYERS - 1) {
            mmagemm16<2,0><<<gN, 256, SMEM_GEMM>>>(a16, slotO, ring_bo + bOff, ring_bo + bOff,
                                                   ring_bo + bOff, nullptr, nodes, M_nodes, NH,
                                                   nullptr);
        } else {
            // last layer: fuse per-tile column max for the final reduction
            mmagemm16<2,2><<<gN, 256, SMEM_GEMM>>>(a16, slotO, ring_bo + bOff, ring_bo + bOff,
                                                   ring_bo + bOff, nullptr, nodes, M_nodes, NH,
                                                   partMax);
        }
    }

    cudaStreamWaitEvent(s0, evJoin[NLAYERS - 1], 0);           // relay ready
    final_fin2_k<<<NB, NH>>>(partMax, relay, out);
}

// round 16
// speedup vs baseline: 1.1678x; 1.0403x over previous
#include <cuda_runtime.h>
#include <cuda_fp16.h>
#include <math.h>
#include <stdint.h>

// ---------------- problem constants ----------------
#define NB 8
#define NL 2048
#define NLP1 2049
#define NH 512
#define NHEADS 8
#define HDIM 64
#define NLAYERS 4

#define MPAD 16512          // 129*128 row capacity (A padding for cp.async)
#define QS 1536             // fused qkv row stride (fp32)

// ---------------- scratch (device globals; no allocation) ----------------
__device__ float g_nodes[(size_t)NB * NL * NH];            // 32 MB
__device__ float g_qkv [(size_t)NB * NLP1 * QS];           // 100 MB (fp32)
__device__ float g_relay[NB * NH];
__device__ float g_attr [NB * NH];
__device__ float g_part [(size_t)2 * 128 * NH];            // tile partials: sum | max
__device__ __align__(16) __half g_a16[(size_t)MPAD * NH];  // 16.9 MB (GEMM A operand)
__device__ __align__(16) __half g_b16[(size_t)(512 + NLAYERS * 2048) * NH]; // 8.9 MB

// =====================================================================
//  low-level helpers
// =====================================================================
__device__ __forceinline__ uint32_t smem_u32(const void* p) {
    uint32_t a;
    asm("{ .reg .u64 t; cvta.to.shared.u64 t, %1; cvt.u32.u64 %0, t; }"
        : "=r"(a) : "l"(p));
    return a;
}

#define CP_ASYNC16(dst, src) \
    asm volatile("cp.async.cg.shared.global [%0], [%1], 16;" \
        :: "r"(dst), "l"(src) : "memory")
#define CP_COMMIT() asm volatile("cp.async.commit_group;" ::: "memory")
#define CP_WAIT(n)  asm volatile("cp.async.wait_group %0;" :: "n"(n) : "memory")

__device__ __forceinline__ void ldsm4(uint32_t* r, uint32_t addr) {
    asm volatile("ldmatrix.sync.aligned.m8n8.x4.shared.b16 {%0,%1,%2,%3}, [%4];"
        : "=r"(r[0]), "=r"(r[1]), "=r"(r[2]), "=r"(r[3]) : "r"(addr));
}

__device__ __forceinline__ void mma16816f(float* c, const uint32_t* a, const uint32_t* b) {
    asm volatile("mma.sync.aligned.m16n8k16.row.col.f32.f16.f16.f32 "
        "{%0,%1,%2,%3}, {%4,%5,%6,%7}, {%8,%9}, {%0,%1,%2,%3};"
        : "+f"(c[0]), "+f"(c[1]), "+f"(c[2]), "+f"(c[3])
        : "r"(a[0]), "r"(a[1]), "r"(a[2]), "r"(a[3]), "r"(b[0]), "r"(b[1]));
}

// swizzled byte offset within one stage tile: 128 rows x 64B (4 chunks of 16B)
__device__ __forceinline__ uint32_t swz(int row, int chunk) {
    return (uint32_t)(row * 64 + ((chunk ^ ((row >> 1) & 3)) << 4));
}

// =====================================================================
//  fp16 mma.sync GEMM: C[M, CS-cols] = A[M,512] @ Bt[N,512]^T + epilogue
//  tile 128x128, 8 warps (4M x 2N), kblock 32, 4-stage cp.async.
//  EPI 0: +bias +pos_emb ; 1: +bias ; 2: leaky(+bias)
//  RED 0: none ; 1: per-tile column SUM -> redp ; 2: per-tile column MAX
// =====================================================================
#define STG 4
#define STAGE_BYTES 8192
#define SMEM_GEMM (2 * STG * STAGE_BYTES)
#define KBLKS 16

template<int EPI, int RED>
__global__ void __launch_bounds__(256, 2)
mmagemm16(const __half* __restrict__ A, const __half* __restrict__ Bt,
          const float* __restrict__ b0p, const float* __restrict__ b1p,
          const float* __restrict__ b2p, const float* __restrict__ extra,
          float* __restrict__ C, int M, int CS, float* __restrict__ redp)
{
    extern __shared__ char smem[];
    const uint32_t aBase = smem_u32(smem);
    const uint32_t bBase = aBase + STG * STAGE_BYTES;
    const int tid = threadIdx.x, wid = tid >> 5, lane = tid & 31;
    const int nt = blockIdx.x, mt = blockIdx.y;
    const int warpM = wid & 3, warpN = wid >> 2;

    const int lrow = tid >> 2, lch = tid & 3;
    const __half* ag0 = A + (size_t)(mt * 128 + lrow) * NH + lch * 8;
    const __half* bg0 = Bt + (size_t)(nt * 128 + lrow) * NH + lch * 8;
    const uint32_t sA0 = swz(lrow, lch), sA1 = swz(lrow + 64, lch);

#define LOAD_STAGE(kb, stg) do { \
    const __half* _ag = ag0 + (kb) * 32; \
    const __half* _bg = bg0 + (kb) * 32; \
    uint32_t _da = aBase + (stg) * STAGE_BYTES; \
    uint32_t _db = bBase + (stg) * STAGE_BYTES; \
    CP_ASYNC16(_da + sA0, _ag); \
    CP_ASYNC16(_da + sA1, _ag + (size_t)64 * NH); \
    CP_ASYNC16(_db + sA0, _bg); \
    CP_ASYNC16(_db + sA1, _bg + (size_t)64 * NH); \
    CP_COMMIT(); \
} while (0)

    LOAD_STAGE(0, 0);
    LOAD_STAGE(1, 1);
    LOAD_STAGE(2, 2);

    const int lr = lane & 7;
    const int aRowB = warpM * 32 + lr + ((lane >> 3) & 1) * 8;
    const int aChB  = (lane >> 4);
    const int bRowB = warpN * 64 + lr + (lane >> 4) * 8;
    const int bChB  = (lane >> 3) & 1;

    float acc[64];
#pragma unroll
    for (int i = 0; i < 64; i++) acc[i] = 0.f;

    for (int kb = 0; kb < KBLKS; kb++) {
        const int stg = kb & 3;
        CP_WAIT(2);
        __syncthreads();
        if (kb + 3 < KBLKS) LOAD_STAGE(kb + 3, (kb + 3) & 3);

        const uint32_t da = aBase + stg * STAGE_BYTES;
        const uint32_t db = bBase + stg * STAGE_BYTES;
#pragma unroll
        for (int ks = 0; ks < 2; ks++) {
            uint32_t af[2][4];
#pragma unroll
            for (int mi = 0; mi < 2; mi++)
                ldsm4(af[mi], da + swz(aRowB + mi * 16, ks * 2 + aChB));
#pragma unroll
            for (int p = 0; p < 4; p++) {
                uint32_t bf[4];
                ldsm4(bf, db + swz(bRowB + p * 16, ks * 2 + bChB));
#pragma unroll
                for (int mi = 0; mi < 2; mi++) {
                    mma16816f(&acc[(mi * 8 + 2 * p + 0) * 4], af[mi], bf + 0);
                    mma16816f(&acc[(mi * 8 + 2 * p + 1) * 4], af[mi], bf + 2);
                }
            }
        }
    }

    float r0[8], r1[8];
    if (RED) {
#pragma unroll
        for (int i = 0; i < 8; i++) {
            r0[i] = (RED == 1) ? 0.f : -3.4e38f;
            r1[i] = (RED == 1) ? 0.f : -3.4e38f;
        }
    }

#pragma unroll
    for (int mi = 0; mi < 2; mi++) {
#pragma unroll
        for (int ntile = 0; ntile < 8; ntile++) {
            const float* c = &acc[(mi * 8 + ntile) * 4];
            int row0 = mt * 128 + warpM * 32 + mi * 16 + (lane >> 2);
            int col  = nt * 128 + warpN * 64 + ntile * 8 + (lane & 3) * 2;
            int seg = col >> 9;
            const float* bp = (seg == 0) ? b0p : (seg == 1) ? b1p : b2p;
            int cl = col & 511;
            float bb0 = bp[cl], bb1 = bp[cl + 1];
#pragma unroll
            for (int half0 = 0; half0 < 2; half0++) {
                int row = row0 + half0 * 8;
                if (row >= M) continue;
                float2 o;
                o.x = c[half0 * 2 + 0] + bb0;
                o.y = c[half0 * 2 + 1] + bb1;
                if (EPI == 0) {
                    const float* e = extra + (size_t)(row & (NL - 1)) * NH + col;
                    o.x += e[0]; o.y += e[1];
                }
                if (EPI == 2) {
                    o.x = o.x > 0.f ? o.x : 0.2f * o.x;
                    o.y = o.y > 0.f ? o.y : 0.2f * o.y;
                }
                if (RED == 1) { r0[ntile] += o.x; r1[ntile] += o.y; }
                if (RED == 2) { r0[ntile] = fmaxf(r0[ntile], o.x);
                                r1[ntile] = fmaxf(r1[ntile], o.y); }
                *(float2*)(C + (size_t)row * CS + col) = o;
            }
        }
    }

    if (RED) {
#pragma unroll
        for (int o = 4; o <= 16; o <<= 1) {
#pragma unroll
            for (int i = 0; i < 8; i++) {
                float t0 = __shfl_xor_sync(0xffffffffu, r0[i], o);
                float t1 = __shfl_xor_sync(0xffffffffu, r1[i], o);
                if (RED == 1) { r0[i] += t0; r1[i] += t1; }
                else          { r0[i] = fmaxf(r0[i], t0); r1[i] = fmaxf(r1[i], t1); }
            }
        }
        CP_WAIT(0);
        __syncthreads();
        float* redbuf = (float*)smem;            // [4][128]
        if (lane < 4) {
#pragma unroll
            for (int i = 0; i < 8; i++) {
                int cl = warpN * 64 + i * 8 + lane * 2;
                redbuf[warpM * 128 + cl]     = r0[i];
                redbuf[warpM * 128 + cl + 1] = r1[i];
            }
        }
        __syncthreads();
        if (tid < 128) {
            float v;
            if (RED == 1)
                v = redbuf[tid] + redbuf[128 + tid] + redbuf[256 + tid] + redbuf[384 + tid];
            else
                v = fmaxf(fmaxf(redbuf[tid], redbuf[128 + tid]),
                          fmaxf(redbuf[256 + tid], redbuf[384 + tid]));
            redp[(size_t)mt * NH + nt * 128 + tid] = v;
        }
    }
#undef LOAD_STAGE
}

// ---------------- A conversion: fp32 -> fp16 (for `data` only) --------------
__global__ __launch_bounds__(256) void convA16_k(const float* __restrict__ in,
                                                 __half* __restrict__ out, int n4)
{
    int i = blockIdx.x * 256 + threadIdx.x;
    if (i >= n4) return;
    float4 x = ((const float4*)in)[i];
    ((__half2*)out)[i * 2]     = __floats2half2_rn(x.x, x.y);
    ((__half2*)out)[i * 2 + 1] = __floats2half2_rn(x.z, x.w);
}

// ---------------- ALL weight transposes -> fp16 in ONE launch ---------------
__global__ __launch_bounds__(256) void convB_all_k(
    const float* __restrict__ fc_w, const float* __restrict__ wq,
    const float* __restrict__ wk,   const float* __restrict__ wv,
    const float* __restrict__ wo,   __half* __restrict__ b16)
{
    __shared__ float t[32][33];
    int s = blockIdx.z;
    const float* W;
    __half* Bt;
    if (s == 0) {
        W = fc_w; Bt = b16;
    } else {
        int i = (s - 1) >> 2, j = (s - 1) & 3;
        const float* src = (j == 0) ? wq : (j == 1) ? wk : (j == 2) ? wv : wo;
        W  = src + (size_t)i * NH * NH;
        Bt = b16 + (size_t)(512 + i * 2048 + j * 512) * NH;
    }
    int k0 = blockIdx.x * 32, n0 = blockIdx.y * 32;
    int tx = threadIdx.x & 31, ty = threadIdx.x >> 5;
#pragma unroll
    for (int i = 0; i < 32; i += 8)
        t[ty + i][tx] = W[(size_t)(k0 + ty + i) * NH + n0 + tx];
    __syncthreads();
#pragma unroll
    for (int i = 0; i < 32; i += 8) {
        int n = n0 + ty + i, k = k0 + tx;
        Bt[(size_t)n * NH + k] = __float2half_rn(t[tx][ty + i]);
    }
}

// ---------------- relay from tile partials (16 tiles per batch) -------------
__global__ void relay_fin2_k(const float* __restrict__ part, float* __restrict__ relay)
{
    int b = blockIdx.x, j = threadIdx.x;   // 512 threads
    float s = 0.f;
#pragma unroll
    for (int t = 0; t < 16; t++) s += part[(size_t)(b * 16 + t) * NH + j];
    relay[b * NH + j] = s * (1.f / NL);
}

// ---------------- LayerNorm + concat relay -> a16 (fp16), WARP-PER-ROW ------
// 8 warps per block, each warp owns one row: lane loads 16 floats (4x float4),
// pure shuffle reduction (no barriers, no smem). Relay rows are per-warp
// passthrough -> no divergent-barrier hazard.
__global__ __launch_bounds__(256) void ln_concat_k(
    const float* __restrict__ nodes, const float* __restrict__ relay,
    const float* __restrict__ gamma, const float* __restrict__ beta,
    __half* __restrict__ a16)
{
    int wid = threadIdx.x >> 5, lane = threadIdx.x & 31;
    int row = blockIdx.x * 8 + wid;            // grid = 16392/8 = 2049 blocks
    int b = row / NLP1, l = row - b * NLP1;
    __half2* dst = (__half2*)(a16 + (size_t)row * NH);

    if (l == NL) {                             // relay passthrough
        const float4* src = (const float4*)(relay + b * NH);
#pragma unroll
        for (int i = 0; i < 4; i++) {
            float4 x = src[lane + i * 32];
            dst[(lane + i * 32) * 2]     = __floats2half2_rn(x.x, x.y);
            dst[(lane + i * 32) * 2 + 1] = __floats2half2_rn(x.z, x.w);
        }
        return;
    }
    const float4* src = (const float4*)(nodes + ((size_t)b * NL + l) * NH);
    float4 x[4];
    float s = 0.f, ss = 0.f;
#pragma unroll
    for (int i = 0; i < 4; i++) {
        x[i] = src[lane + i * 32];
        s  += x[i].x + x[i].y + x[i].z + x[i].w;
        ss += x[i].x * x[i].x + x[i].y * x[i].y + x[i].z * x[i].z + x[i].w * x[i].w;
    }
#pragma unroll
    for (int o = 16; o; o >>= 1) {
        s  += __shfl_xor_sync(0xffffffffu, s,  o);
        ss += __shfl_xor_sync(0xffffffffu, ss, o);
    }
    float mu = s * (1.f / NH);
    float var = ss * (1.f / NH) - mu * mu;
    float inv = rsqrtf(var + 1e-6f);
    const float4* gp = (const float4*)gamma;
    const float4* bp = (const float4*)beta;
#pragma unroll
    for (int i = 0; i < 4; i++) {
        float4 g = gp[lane + i * 32];
        float4 bb = bp[lane + i * 32];
        float ox = (x[i].x - mu) * inv * g.x + bb.x;
        float oy = (x[i].y - mu) * inv * g.y + bb.y;
        float oz = (x[i].z - mu) * inv * g.z + bb.z;
        float ow = (x[i].w - mu) * inv * g.w + bb.w;
        dst[(lane + i * 32) * 2]     = __floats2half2_rn(ox, oy);
        dst[(lane + i * 32) * 2 + 1] = __floats2half2_rn(oz, ow);
    }
}

// ---------------- ring attention (fp32 qkv) -> a16 (fp16), 2 l per warp -----
__global__ __launch_bounds__(256) void ring_attn_k(
    const float* __restrict__ qkv, __half* __restrict__ a16)
{
    int gw = blockIdx.x * 8 + (threadIdx.x >> 5);
    int lane = threadIdx.x & 31;
    int h = gw & 7;
    int l0 = ((gw >> 3) & 1023) * 2;
    int b = gw >> 13;
    size_t rb = (size_t)b * NLP1 * QS + (size_t)h * HDIM + lane * 2;

    const float* qq = qkv + rb;
    const float* kk = qkv + rb + 512;
    const float* vv = qkv + rb + 1024;
    float2 z = make_float2(0.f, 0.f);

    float2 q0 = *(const float2*)(qq + (size_t)l0 * QS);
    float2 q1 = *(const float2*)(qq + (size_t)(l0 + 1) * QS);

    float2 k0 = (l0 > 0)      ? *(const float2*)(kk + (size_t)(l0 - 1) * QS) : z;
    float2 k1 =                 *(const float2*)(kk + (size_t)l0       * QS);
    float2 k2 =                 *(const float2*)(kk + (size_t)(l0 + 1) * QS);
    float2 k3 = (l0 + 2 < NL) ? *(const float2*)(kk + (size_t)(l0 + 2) * QS) : z;
    float2 kr =                 *(const float2*)(kk + (size_t)NL       * QS);

    float a0 = q0.x * k0.x + q0.y * k0.y;
    float a1 = q0.x * k1.x + q0.y * k1.y;
    float a2 = q0.x * k2.x + q0.y * k2.y;
    float a3 = q0.x * kr.x + q0.y * kr.y;
    float c0 = q1.x * k1.x + q1.y * k1.y;
    float c1 = q1.x * k2.x + q1.y * k2.y;
    float c2 = q1.x * k3.x + q1.y * k3.y;
    float c3 = q1.x * kr.x + q1.y * kr.y;
#pragma unroll
    for (int o = 16; o; o >>= 1) {
        a0 += __shfl_xor_sync(0xffffffffu, a0, o);
        a1 += __shfl_xor_sync(0xffffffffu, a1, o);
        a2 += __shfl_xor_sync(0xffffffffu, a2, o);
        a3 += __shfl_xor_sync(0xffffffffu, a3, o);
        c0 += __shfl_xor_sync(0xffffffffu, c0, o);
        c1 += __shfl_xor_sync(0xffffffffu, c1, o);
        c2 += __shfl_xor_sync(0xffffffffu, c2, o);
        c3 += __shfl_xor_sync(0xffffffffu, c3, o);
    }
    const float scale = 0.125f;
    a0 *= scale; a1 *= scale; a2 *= scale; a3 *= scale;
    c0 *= scale; c1 *= scale; c2 *= scale; c3 *= scale;

    float m0 = fmaxf(fmaxf(a0, a1), fmaxf(a2, a3));
    float e00 = __expf(a0 - m0), e01 = __expf(a1 - m0);
    float e02 = __expf(a2 - m0), e03 = __expf(a3 - m0);
    float inv0 = 1.f / (e00 + e01 + e02 + e03);

    float m1 = fmaxf(fmaxf(c0, c1), fmaxf(c2, c3));
    float e10 = __expf(c0 - m1), e11 = __expf(c1 - m1);
    float e12 = __expf(c2 - m1), e13 = __expf(c3 - m1);
    float inv1 = 1.f / (e10 + e11 + e12 + e13);

    float2 v0 = (l0 > 0)      ? *(const float2*)(vv + (size_t)(l0 - 1) * QS) : z;
    float2 v1 =                 *(const float2*)(vv + (size_t)l0       * QS);
    float2 v2 =                 *(const float2*)(vv + (size_t)(l0 + 1) * QS);
    float2 v3 = (l0 + 2 < NL) ? *(const float2*)(vv + (size_t)(l0 + 2) * QS) : z;
    float2 vr =                 *(const float2*)(vv + (size_t)NL       * QS);

    float ox0 = (e00 * v0.x + e01 * v1.x + e02 * v2.x + e03 * vr.x) * inv0;
    float oy0 = (e00 * v0.y + e01 * v1.y + e02 * v2.y + e03 * vr.y) * inv0;
    float ox1 = (e10 * v1.x + e11 * v2.x + e12 * v3.x + e13 * vr.x) * inv1;
    float oy1 = (e10 * v1.y + e11 * v2.y + e12 * v3.y + e13 * vr.y) * inv1;

    __half2* d0 = (__half2*)(a16 + ((size_t)b * NL + l0) * NH + (size_t)h * HDIM);
    __half2* d1 = (__half2*)(a16 + ((size_t)b * NL + l0 + 1) * NH + (size_t)h * HDIM);
    d0[lane] = __floats2half2_rn(ox0, oy0);
    d1[lane] = __floats2half2_rn(ox1, oy1);
}

// ---------------- star attention (fp32 qkv) ----------------
__global__ __launch_bounds__(256) void star_attn_k(
    const float* __restrict__ qkv, float* __restrict__ attr)
{
    __shared__ float sq[HDIM];
    __shared__ float sc[NLP1];
    __shared__ float red[8];
    __shared__ float part[4][HDIM];
    int b = blockIdx.x >> 3, h = blockIdx.x & 7;
    int tid = threadIdx.x;
    size_t hb = (size_t)b * NLP1 * QS + (size_t)h * HDIM;
    if (tid < HDIM) sq[tid] = qkv[hb + (size_t)NL * QS + tid];
    __syncthreads();
    float lmax = -1e30f;
    for (int l = tid; l < NLP1; l += 256) {
        const float4* kp = (const float4*)(qkv + hb + 512 + (size_t)l * QS);
        float d = 0.f;
#pragma unroll
        for (int j = 0; j < HDIM / 4; j++) {
            float4 kk = kp[j];
            d += sq[4 * j + 0] * kk.x + sq[4 * j + 1] * kk.y
               + sq[4 * j + 2] * kk.z + sq[4 * j + 3] * kk.w;
        }
        d *= 0.125f;
        sc[l] = d;
        lmax = fmaxf(lmax, d);
    }
    int lane = tid & 31, w = tid >> 5;
#pragma unroll
    for (int o = 16; o; o >>= 1) lmax = fmaxf(lmax, __shfl_xor_sync(0xffffffffu, lmax, o));
    if (lane == 0) red[w] = lmax;
    __syncthreads();
    if (tid == 0) {
        float m = red[0];
#pragma unroll
        for (int i = 1; i < 8; i++) m = fmaxf(m, red[i]);
        red[0] = m;
    }
    __syncthreads();
    float m = red[0];
    __syncthreads();
    float lsum = 0.f;
    for (int l = tid; l < NLP1; l += 256) {
        float e = __expf(sc[l] - m);
        sc[l] = e;
        lsum += e;
    }
#pragma unroll
    for (int o = 16; o; o >>= 1) lsum += __shfl_xor_sync(0xffffffffu, lsum, o);
    if (lane == 0) red[w] = lsum;
    __syncthreads();
    if (tid == 0) {
        float s = 0.f;
#pragma unroll
        for (int i = 0; i < 8; i++) s += red[i];
        red[0] = s;
    }
    __syncthreads();
    float Zinv = 1.f / red[0];
    int d = tid & 63, g = tid >> 6;
    float acc = 0.f;
    for (int l = g; l < NLP1; l += 4)
        acc += sc[l] * qkv[hb + 1024 + (size_t)l * QS + d];
    part[g][d] = acc;
    __syncthreads();
    if (tid < HDIM)
        attr[(size_t)b * NH + h * HDIM + tid] =
            (part[0][tid] + part[1][tid] + part[2][tid] + part[3][tid]) * Zinv;
}

// ---------------- star output GEMM + leaky ----------------
__global__ __launch_bounds__(256) void star_out_k(
    const float* __restrict__ attr, const float* __restrict__ w,
    const float* __restrict__ bias, float* __restrict__ relay)
{
    __shared__ float sa[512];
    __shared__ float red[4][64];
    int b = blockIdx.y, cx = blockIdx.x;
    int t = threadIdx.x;
    sa[t]       = attr[b * NH + t];
    sa[t + 256] = attr[b * NH + t + 256];
    __syncthreads();
    int col = cx * 64 + (t & 63), g = t >> 6;
    float acc = 0.f;
    const float* wp = w + (size_t)(g * 128) * NH + col;
#pragma unroll 4
    for (int kk = 0; kk < 128; kk++)
        acc += sa[g * 128 + kk] * wp[(size_t)kk * NH];
    red[g][t & 63] = acc;
    __syncthreads();
    if (t < 64) {
        float a = red[0][t] + red[1][t] + red[2][t] + red[3][t] + bias[cx * 64 + t];
        relay[b * NH + cx * 64 + t] = a > 0.f ? a : 0.2f * a;
    }
}

// ---------------- final from tile partials + relay ----------------
__global__ void final_fin2_k(const float* __restrict__ partmax,
                             const float* __restrict__ relay, float* __restrict__ out)
{
    int b = blockIdx.x, j = threadIdx.x;   // 512 threads
    float m = -3.4e38f;
#pragma unroll
    for (int t = 0; t < 16; t++) m = fmaxf(m, partmax[(size_t)(b * 16 + t) * NH + j]);
    out[b * NH + j] = 0.5f * (relay[b * NH + j] + m);
}

// =====================================================================
//  host launch
// =====================================================================
extern "C" void kernel_launch(void* const* d_in, const int* in_sizes, int n_in,
                              void* d_out, int out_size)
{
    const float* data    = (const float*)d_in[0];
    const float* fc_w    = (const float*)d_in[1];
    const float* fc_b    = (const float*)d_in[2];
    const float* pos_emb = (const float*)d_in[3];
    const float* ln_g    = (const float*)d_in[4];
    const float* ln_b    = (const float*)d_in[5];
    const float* wq      = (const float*)d_in[6];
    const float* wk      = (const float*)d_in[7];
    const float* wv      = (const float*)d_in[8];
    const float* bq      = (const float*)d_in[9];
    const float* bk      = (const float*)d_in[10];
    const float* bv      = (const float*)d_in[11];
    const float* ring_wo = (const float*)d_in[12];
    const float* ring_bo = (const float*)d_in[13];
    const float* star_wo = (const float*)d_in[14];
    const float* star_bo = (const float*)d_in[15];
    float* out = (float*)d_out;

    float *nodes, *qkv, *relay, *attr, *part;
    __half *a16, *b16;
    cudaGetSymbolAddress((void**)&nodes, g_nodes);
    cudaGetSymbolAddress((void**)&qkv,   g_qkv);
    cudaGetSymbolAddress((void**)&relay, g_relay);
    cudaGetSymbolAddress((void**)&attr,  g_attr);
    cudaGetSymbolAddress((void**)&part,  g_part);
    cudaGetSymbolAddress((void**)&a16,   g_a16);
    cudaGetSymbolAddress((void**)&b16,   g_b16);
    float* partSum = part;
    float* partMax = part + (size_t)128 * NH;

    static bool init_done = false;
    static cudaStream_t s2;
    static cudaEvent_t evFork[NLAYERS], evJoin[NLAYERS], evFork0, evConvB;
    if (!init_done) {
        cudaFuncSetAttribute(mmagemm16<0,1>, cudaFuncAttributeMaxDynamicSharedMemorySize, SMEM_GEMM);
        cudaFuncSetAttribute(mmagemm16<1,0>, cudaFuncAttributeMaxDynamicSharedMemorySize, SMEM_GEMM);
        cudaFuncSetAttribute(mmagemm16<2,0>, cudaFuncAttributeMaxDynamicSharedMemorySize, SMEM_GEMM);
        cudaFuncSetAttribute(mmagemm16<2,2>, cudaFuncAttributeMaxDynamicSharedMemorySize, SMEM_GEMM);
        cudaStreamCreateWithFlags(&s2, cudaStreamNonBlocking);
        for (int i = 0; i < NLAYERS; i++) {
            cudaEventCreateWithFlags(&evFork[i], cudaEventDisableTiming);
            cudaEventCreateWithFlags(&evJoin[i], cudaEventDisableTiming);
        }
        cudaEventCreateWithFlags(&evFork0, cudaEventDisableTiming);
        cudaEventCreateWithFlags(&evConvB, cudaEventDisableTiming);
        init_done = true;
    }
    cudaStream_t s0 = (cudaStream_t)0;

    const int M_nodes = NB * NL;     // 16384
    const int M_xy    = NB * NLP1;   // 16392
    dim3 gN(4, M_nodes / 128);       // (4,128)  N=512
    dim3 gQKV(12, (M_xy + 127) / 128); // (12,129) N=1536

    // ---- fork s2 from origin (graph-capture rule); convB on s2 ∥ convA on s0
    cudaEventRecord(evFork0, s0);
    cudaStreamWaitEvent(s2, evFork0, 0);
    convB_all_k<<<dim3(16, 16, 1 + NLAYERS * 4), 256, 0, s2>>>(fc_w, wq, wk, wv, ring_wo, b16);
    cudaEventRecord(evConvB, s2);
    convA16_k<<<(M_nodes * 128 + 255) / 256, 256>>>(data, a16, M_nodes * 128);
    cudaStreamWaitEvent(s0, evConvB, 0);

    // ---- embeddings: GEMM with fused per-tile column sums -> relay ----
    mmagemm16<0,1><<<gN, 256, SMEM_GEMM>>>(a16, b16, fc_b, fc_b, fc_b, pos_emb,
                                           nodes, M_nodes, NH, partSum);
    relay_fin2_k<<<NB, NH>>>(partSum, relay);

    for (int i = 0; i < NLAYERS; i++) {
        size_t bOff = (size_t)i * 512;
        __half* slot  = b16 + (size_t)(512 + i * 2048) * NH;
        __half* slotO = slot + (size_t)1536 * NH;

        if (i > 0) cudaStreamWaitEvent(s0, evJoin[i - 1], 0);  // relay ready
        ln_concat_k<<<(NB * NLP1) / 8, 256>>>(nodes, relay, ln_g + bOff, ln_b + bOff, a16);

        mmagemm16<1,0><<<gQKV, 256, SMEM_GEMM>>>(a16, slot, bq + bOff, bk + bOff,
                                                 bv + bOff, nullptr, qkv, M_xy, QS, nullptr);

        // fork: star branch on s2 (depends only on qkv), overlaps ring branch
        cudaEventRecord(evFork[i], s0);
        cudaStreamWaitEvent(s2, evFork[i], 0);
        star_attn_k<<<NB * NHEADS, 256, 0, s2>>>(qkv, attr);
        star_out_k<<<dim3(8, NB), 256, 0, s2>>>(attr, star_wo + (size_t)i * 512 * 512,
                                                star_bo + bOff, relay);
        cudaEventRecord(evJoin[i], s2);

        ring_attn_k<<<NB * NHEADS * 1024 / 8, 256>>>(qkv, a16);
        if (i < NLAYERS - 1) {
            mmagemm16<2,0><<<gN, 256, SMEM_GEMM>>>(a16, slotO, ring_bo + bOff, ring_bo + bOff,
                                                   ring_bo + bOff, nullptr, nodes, M_nodes, NH,
                                                   nullptr);
        } else {
            mmagemm16<2,2><<<gN, 256, SMEM_GEMM>>>(a16, slotO, ring_bo + bOff, ring_bo + bOff,
                                                   ring_bo + bOff, nullptr, nodes, M_nodes, NH,
                                                   partMax);
        }
    }

    cudaStreamWaitEvent(s0, evJoin[NLAYERS - 1], 0);           // relay ready
    final_fin2_k<<<NB, NH>>>(partMax, relay, out);
}

// round 17
// speedup vs baseline: 1.1770x; 1.0078x over previous
#include <cuda_runtime.h>
#include <cuda_fp16.h>
#include <math.h>
#include <stdint.h>

// ---------------- problem constants ----------------
#define NB 8
#define NL 2048
#define NLP1 2049
#define NH 512
#define NHEADS 8
#define HDIM 64
#define NLAYERS 4

#define MPAD 16512          // 129*128 row capacity (A padding for cp.async)
#define QS 1536             // fused qkv row stride (fp32)

// ---------------- scratch (device globals; no allocation) ----------------
__device__ float g_nodes[(size_t)NB * NL * NH];            // 32 MB
__device__ float g_qkv [(size_t)NB * NLP1 * QS];           // 100 MB (fp32)
__device__ float g_relay[NB * NH];
__device__ float g_attr [NB * NH];
__device__ float g_part [(size_t)2 * 128 * NH];            // tile partials: sum | max
__device__ __align__(16) __half g_a16[(size_t)MPAD * NH];  // 16.9 MB (GEMM A operand)
__device__ __align__(16) __half g_b16[(size_t)(512 + NLAYERS * 2048) * NH]; // 8.9 MB

// =====================================================================
//  low-level helpers
// =====================================================================
__device__ __forceinline__ uint32_t smem_u32(const void* p) {
    uint32_t a;
    asm("{ .reg .u64 t; cvta.to.shared.u64 t, %1; cvt.u32.u64 %0, t; }"
        : "=r"(a) : "l"(p));
    return a;
}

#define CP_ASYNC16(dst, src) \
    asm volatile("cp.async.cg.shared.global [%0], [%1], 16;" \
        :: "r"(dst), "l"(src) : "memory")
#define CP_COMMIT() asm volatile("cp.async.commit_group;" ::: "memory")
#define CP_WAIT(n)  asm volatile("cp.async.wait_group %0;" :: "n"(n) : "memory")

__device__ __forceinline__ void ldsm4(uint32_t* r, uint32_t addr) {
    asm volatile("ldmatrix.sync.aligned.m8n8.x4.shared.b16 {%0,%1,%2,%3}, [%4];"
        : "=r"(r[0]), "=r"(r[1]), "=r"(r[2]), "=r"(r[3]) : "r"(addr));
}

__device__ __forceinline__ void mma16816f(float* c, const uint32_t* a, const uint32_t* b) {
    asm volatile("mma.sync.aligned.m16n8k16.row.col.f32.f16.f16.f32 "
        "{%0,%1,%2,%3}, {%4,%5,%6,%7}, {%8,%9}, {%0,%1,%2,%3};"
        : "+f"(c[0]), "+f"(c[1]), "+f"(c[2]), "+f"(c[3])
        : "r"(a[0]), "r"(a[1]), "r"(a[2]), "r"(a[3]), "r"(b[0]), "r"(b[1]));
}

// swizzled byte offset within one stage tile: 128 rows x 64B (4 chunks of 16B)
__device__ __forceinline__ uint32_t swz(int row, int chunk) {
    return (uint32_t)(row * 64 + ((chunk ^ ((row >> 1) & 3)) << 4));
}

// =====================================================================
//  fp16 mma.sync GEMM: C[M, CS-cols] = A[M,512] @ Bt[N,512]^T + epilogue
//  tile 128x128, 8 warps (4M x 2N), kblock 32, 4-stage cp.async.
//  EPI 0: +bias +pos_emb ; 1: +bias ; 2: leaky(+bias)
//  RED 0: none ; 1: per-tile column SUM -> redp ; 2: per-tile column MAX
// =====================================================================
#define STG 4
#define STAGE_BYTES 8192
#define SMEM_GEMM (2 * STG * STAGE_BYTES)
#define KBLKS 16

template<int EPI, int RED>
__global__ void __launch_bounds__(256, 2)
mmagemm16(const __half* __restrict__ A, const __half* __restrict__ Bt,
          const float* __restrict__ b0p, const float* __restrict__ b1p,
          const float* __restrict__ b2p, const float* __restrict__ extra,
          float* __restrict__ C, int M, int CS, float* __restrict__ redp)
{
    extern __shared__ char smem[];
    const uint32_t aBase = smem_u32(smem);
    const uint32_t bBase = aBase + STG * STAGE_BYTES;
    const int tid = threadIdx.x, wid = tid >> 5, lane = tid & 31;
    const int nt = blockIdx.x, mt = blockIdx.y;
    const int warpM = wid & 3, warpN = wid >> 2;

    const int lrow = tid >> 2, lch = tid & 3;
    const __half* ag0 = A + (size_t)(mt * 128 + lrow) * NH + lch * 8;
    const __half* bg0 = Bt + (size_t)(nt * 128 + lrow) * NH + lch * 8;
    const uint32_t sA0 = swz(lrow, lch), sA1 = swz(lrow + 64, lch);

#define LOAD_STAGE(kb, stg) do { \
    const __half* _ag = ag0 + (kb) * 32; \
    const __half* _bg = bg0 + (kb) * 32; \
    uint32_t _da = aBase + (stg) * STAGE_BYTES; \
    uint32_t _db = bBase + (stg) * STAGE_BYTES; \
    CP_ASYNC16(_da + sA0, _ag); \
    CP_ASYNC16(_da + sA1, _ag + (size_t)64 * NH); \
    CP_ASYNC16(_db + sA0, _bg); \
    CP_ASYNC16(_db + sA1, _bg + (size_t)64 * NH); \
    CP_COMMIT(); \
} while (0)

    LOAD_STAGE(0, 0);
    LOAD_STAGE(1, 1);
    LOAD_STAGE(2, 2);

    const int lr = lane & 7;
    const int aRowB = warpM * 32 + lr + ((lane >> 3) & 1) * 8;
    const int aChB  = (lane >> 4);
    const int bRowB = warpN * 64 + lr + (lane >> 4) * 8;
    const int bChB  = (lane >> 3) & 1;

    float acc[64];
#pragma unroll
    for (int i = 0; i < 64; i++) acc[i] = 0.f;

    for (int kb = 0; kb < KBLKS; kb++) {
        const int stg = kb & 3;
        CP_WAIT(2);
        __syncthreads();
        if (kb + 3 < KBLKS) LOAD_STAGE(kb + 3, (kb + 3) & 3);

        const uint32_t da = aBase + stg * STAGE_BYTES;
        const uint32_t db = bBase + stg * STAGE_BYTES;
#pragma unroll
        for (int ks = 0; ks < 2; ks++) {
            uint32_t af[2][4];
#pragma unroll
            for (int mi = 0; mi < 2; mi++)
                ldsm4(af[mi], da + swz(aRowB + mi * 16, ks * 2 + aChB));
#pragma unroll
            for (int p = 0; p < 4; p++) {
                uint32_t bf[4];
                ldsm4(bf, db + swz(bRowB + p * 16, ks * 2 + bChB));
#pragma unroll
                for (int mi = 0; mi < 2; mi++) {
                    mma16816f(&acc[(mi * 8 + 2 * p + 0) * 4], af[mi], bf + 0);
                    mma16816f(&acc[(mi * 8 + 2 * p + 1) * 4], af[mi], bf + 2);
                }
            }
        }
    }

    float r0[8], r1[8];
    if (RED) {
#pragma unroll
        for (int i = 0; i < 8; i++) {
            r0[i] = (RED == 1) ? 0.f : -3.4e38f;
            r1[i] = (RED == 1) ? 0.f : -3.4e38f;
        }
    }

#pragma unroll
    for (int mi = 0; mi < 2; mi++) {
#pragma unroll
        for (int ntile = 0; ntile < 8; ntile++) {
            const float* c = &acc[(mi * 8 + ntile) * 4];
            int row0 = mt * 128 + warpM * 32 + mi * 16 + (lane >> 2);
            int col  = nt * 128 + warpN * 64 + ntile * 8 + (lane & 3) * 2;
            int seg = col >> 9;
            const float* bp = (seg == 0) ? b0p : (seg == 1) ? b1p : b2p;
            int cl = col & 511;
            float bb0 = bp[cl], bb1 = bp[cl + 1];
#pragma unroll
            for (int half0 = 0; half0 < 2; half0++) {
                int row = row0 + half0 * 8;
                if (row >= M) continue;
                float2 o;
                o.x = c[half0 * 2 + 0] + bb0;
                o.y = c[half0 * 2 + 1] + bb1;
                if (EPI == 0) {
                    const float* e = extra + (size_t)(row & (NL - 1)) * NH + col;
                    o.x += e[0]; o.y += e[1];
                }
                if (EPI == 2) {
                    o.x = o.x > 0.f ? o.x : 0.2f * o.x;
                    o.y = o.y > 0.f ? o.y : 0.2f * o.y;
                }
                if (RED == 1) { r0[ntile] += o.x; r1[ntile] += o.y; }
                if (RED == 2) { r0[ntile] = fmaxf(r0[ntile], o.x);
                                r1[ntile] = fmaxf(r1[ntile], o.y); }
                *(float2*)(C + (size_t)row * CS + col) = o;
            }
        }
    }

    if (RED) {
#pragma unroll
        for (int o = 4; o <= 16; o <<= 1) {
#pragma unroll
            for (int i = 0; i < 8; i++) {
                float t0 = __shfl_xor_sync(0xffffffffu, r0[i], o);
                float t1 = __shfl_xor_sync(0xffffffffu, r1[i], o);
                if (RED == 1) { r0[i] += t0; r1[i] += t1; }
                else          { r0[i] = fmaxf(r0[i], t0); r1[i] = fmaxf(r1[i], t1); }
            }
        }
        CP_WAIT(0);
        __syncthreads();
        float* redbuf = (float*)smem;            // [4][128]
        if (lane < 4) {
#pragma unroll
            for (int i = 0; i < 8; i++) {
                int cl = warpN * 64 + i * 8 + lane * 2;
                redbuf[warpM * 128 + cl]     = r0[i];
                redbuf[warpM * 128 + cl + 1] = r1[i];
            }
        }
        __syncthreads();
        if (tid < 128) {
            float v;
            if (RED == 1)
                v = redbuf[tid] + redbuf[128 + tid] + redbuf[256 + tid] + redbuf[384 + tid];
            else
                v = fmaxf(fmaxf(redbuf[tid], redbuf[128 + tid]),
                          fmaxf(redbuf[256 + tid], redbuf[384 + tid]));
            redp[(size_t)mt * NH + nt * 128 + tid] = v;
        }
    }
#undef LOAD_STAGE
}

// ---------------- A conversion: fp32 -> fp16 (for `data` only) --------------
__global__ __launch_bounds__(256) void convA16_k(const float* __restrict__ in,
                                                 __half* __restrict__ out, int n4)
{
    int i = blockIdx.x * 256 + threadIdx.x;
    if (i >= n4) return;
    float4 x = ((const float4*)in)[i];
    ((__half2*)out)[i * 2]     = __floats2half2_rn(x.x, x.y);
    ((__half2*)out)[i * 2 + 1] = __floats2half2_rn(x.z, x.w);
}

// ---------------- ALL weight transposes -> fp16 in ONE launch ---------------
__global__ __launch_bounds__(256) void convB_all_k(
    const float* __restrict__ fc_w, const float* __restrict__ wq,
    const float* __restrict__ wk,   const float* __restrict__ wv,
    const float* __restrict__ wo,   __half* __restrict__ b16)
{
    __shared__ float t[32][33];
    int s = blockIdx.z;
    const float* W;
    __half* Bt;
    if (s == 0) {
        W = fc_w; Bt = b16;
    } else {
        int i = (s - 1) >> 2, j = (s - 1) & 3;
        const float* src = (j == 0) ? wq : (j == 1) ? wk : (j == 2) ? wv : wo;
        W  = src + (size_t)i * NH * NH;
        Bt = b16 + (size_t)(512 + i * 2048 + j * 512) * NH;
    }
    int k0 = blockIdx.x * 32, n0 = blockIdx.y * 32;
    int tx = threadIdx.x & 31, ty = threadIdx.x >> 5;
#pragma unroll
    for (int i = 0; i < 32; i += 8)
        t[ty + i][tx] = W[(size_t)(k0 + ty + i) * NH + n0 + tx];
    __syncthreads();
#pragma unroll
    for (int i = 0; i < 32; i += 8) {
        int n = n0 + ty + i, k = k0 + tx;
        Bt[(size_t)n * NH + k] = __float2half_rn(t[tx][ty + i]);
    }
}

// ---------------- relay from tile partials (16 tiles per batch) -------------
__global__ void relay_fin2_k(const float* __restrict__ part, float* __restrict__ relay)
{
    int b = blockIdx.x, j = threadIdx.x;   // 512 threads
    float s = 0.f;
#pragma unroll
    for (int t = 0; t < 16; t++) s += part[(size_t)(b * 16 + t) * NH + j];
    relay[b * NH + j] = s * (1.f / NL);
}

// ---------------- LayerNorm + concat relay -> a16 (fp16), WARP-PER-ROW ------
__global__ __launch_bounds__(256) void ln_concat_k(
    const float* __restrict__ nodes, const float* __restrict__ relay,
    const float* __restrict__ gamma, const float* __restrict__ beta,
    __half* __restrict__ a16)
{
    int wid = threadIdx.x >> 5, lane = threadIdx.x & 31;
    int row = blockIdx.x * 8 + wid;            // grid = 16392/8 = 2049 blocks
    int b = row / NLP1, l = row - b * NLP1;
    __half2* dst = (__half2*)(a16 + (size_t)row * NH);

    if (l == NL) {                             // relay passthrough
        const float4* src = (const float4*)(relay + b * NH);
#pragma unroll
        for (int i = 0; i < 4; i++) {
            float4 x = src[lane + i * 32];
            dst[(lane + i * 32) * 2]     = __floats2half2_rn(x.x, x.y);
            dst[(lane + i * 32) * 2 + 1] = __floats2half2_rn(x.z, x.w);
        }
        return;
    }
    const float4* src = (const float4*)(nodes + ((size_t)b * NL + l) * NH);
    float4 x[4];
    float s = 0.f, ss = 0.f;
#pragma unroll
    for (int i = 0; i < 4; i++) {
        x[i] = src[lane + i * 32];
        s  += x[i].x + x[i].y + x[i].z + x[i].w;
        ss += x[i].x * x[i].x + x[i].y * x[i].y + x[i].z * x[i].z + x[i].w * x[i].w;
    }
#pragma unroll
    for (int o = 16; o; o >>= 1) {
        s  += __shfl_xor_sync(0xffffffffu, s,  o);
        ss += __shfl_xor_sync(0xffffffffu, ss, o);
    }
    float mu = s * (1.f / NH);
    float var = ss * (1.f / NH) - mu * mu;
    float inv = rsqrtf(var + 1e-6f);
    const float4* gp = (const float4*)gamma;
    const float4* bp = (const float4*)beta;
#pragma unroll
    for (int i = 0; i < 4; i++) {
        float4 g = gp[lane + i * 32];
        float4 bb = bp[lane + i * 32];
        float ox = (x[i].x - mu) * inv * g.x + bb.x;
        float oy = (x[i].y - mu) * inv * g.y + bb.y;
        float oz = (x[i].z - mu) * inv * g.z + bb.z;
        float ow = (x[i].w - mu) * inv * g.w + bb.w;
        dst[(lane + i * 32) * 2]     = __floats2half2_rn(ox, oy);
        dst[(lane + i * 32) * 2 + 1] = __floats2half2_rn(oz, ow);
    }
}

// ---------------- ring attention (fp32 qkv) -> a16 (fp16), 4 l per warp -----
// Shares k/v loads across 4 adjacent l: 18 float2 loads per quad vs 24 for
// two pairs. Per-row numerics identical to the 1-l version.
__global__ __launch_bounds__(256) void ring_attn_k(
    const float* __restrict__ qkv, __half* __restrict__ a16)
{
    int gw = blockIdx.x * 8 + (threadIdx.x >> 5);   // 0 .. NB*NHEADS*512-1
    int lane = threadIdx.x & 31;
    int h = gw & 7;
    int l0 = ((gw >> 3) & 511) * 4;                 // quad base
    int b = gw >> 12;
    size_t rb = (size_t)b * NLP1 * QS + (size_t)h * HDIM + lane * 2;

    const float* qq = qkv + rb;
    const float* kk = qkv + rb + 512;
    const float* vv = qkv + rb + 1024;
    float2 z = make_float2(0.f, 0.f);

    float2 q[4];
#pragma unroll
    for (int r = 0; r < 4; r++)
        q[r] = *(const float2*)(qq + (size_t)(l0 + r) * QS);

    // keys l0-1 .. l0+4 (indices 0..5) + relay
    float2 kv[6];
    kv[0] = (l0 > 0)      ? *(const float2*)(kk + (size_t)(l0 - 1) * QS) : z;
#pragma unroll
    for (int i = 1; i < 5; i++)
        kv[i] = *(const float2*)(kk + (size_t)(l0 + i - 1) * QS);
    kv[5] = (l0 + 4 < NL) ? *(const float2*)(kk + (size_t)(l0 + 4) * QS) : z;
    float2 kr = *(const float2*)(kk + (size_t)NL * QS);

    // 16 scores: row r uses kv[r], kv[r+1], kv[r+2], kr
    float sc[4][4];
#pragma unroll
    for (int r = 0; r < 4; r++) {
        sc[r][0] = q[r].x * kv[r].x     + q[r].y * kv[r].y;
        sc[r][1] = q[r].x * kv[r + 1].x + q[r].y * kv[r + 1].y;
        sc[r][2] = q[r].x * kv[r + 2].x + q[r].y * kv[r + 2].y;
        sc[r][3] = q[r].x * kr.x        + q[r].y * kr.y;
    }
#pragma unroll
    for (int o = 16; o; o >>= 1) {
#pragma unroll
        for (int r = 0; r < 4; r++) {
#pragma unroll
            for (int w = 0; w < 4; w++)
                sc[r][w] += __shfl_xor_sync(0xffffffffu, sc[r][w], o);
        }
    }
    const float scale = 0.125f;
    float e[4][4], inv[4];
#pragma unroll
    for (int r = 0; r < 4; r++) {
        float s0 = sc[r][0] * scale, s1 = sc[r][1] * scale;
        float s2 = sc[r][2] * scale, s3 = sc[r][3] * scale;
        float m = fmaxf(fmaxf(s0, s1), fmaxf(s2, s3));
        e[r][0] = __expf(s0 - m); e[r][1] = __expf(s1 - m);
        e[r][2] = __expf(s2 - m); e[r][3] = __expf(s3 - m);
        inv[r] = 1.f / (e[r][0] + e[r][1] + e[r][2] + e[r][3]);
    }

    // values l0-1 .. l0+4 (reuse kv[]) + relay
    kv[0] = (l0 > 0)      ? *(const float2*)(vv + (size_t)(l0 - 1) * QS) : z;
#pragma unroll
    for (int i = 1; i < 5; i++)
        kv[i] = *(const float2*)(vv + (size_t)(l0 + i - 1) * QS);
    kv[5] = (l0 + 4 < NL) ? *(const float2*)(vv + (size_t)(l0 + 4) * QS) : z;
    float2 vr = *(const float2*)(vv + (size_t)NL * QS);

#pragma unroll
    for (int r = 0; r < 4; r++) {
        float ox = (e[r][0] * kv[r].x + e[r][1] * kv[r + 1].x
                  + e[r][2] * kv[r + 2].x + e[r][3] * vr.x) * inv[r];
        float oy = (e[r][0] * kv[r].y + e[r][1] * kv[r + 1].y
                  + e[r][2] * kv[r + 2].y + e[r][3] * vr.y) * inv[r];
        __half2* d = (__half2*)(a16 + ((size_t)b * NL + l0 + r) * NH + (size_t)h * HDIM);
        d[lane] = __floats2half2_rn(ox, oy);
    }
}

// ---------------- star attention (fp32 qkv) ----------------
__global__ __launch_bounds__(256) void star_attn_k(
    const float* __restrict__ qkv, float* __restrict__ attr)
{
    __shared__ float sq[HDIM];
    __shared__ float sc[NLP1];
    __shared__ float red[8];
    __shared__ float part[4][HDIM];
    int b = blockIdx.x >> 3, h = blockIdx.x & 7;
    int tid = threadIdx.x;
    size_t hb = (size_t)b * NLP1 * QS + (size_t)h * HDIM;
    if (tid < HDIM) sq[tid] = qkv[hb + (size_t)NL * QS + tid];
    __syncthreads();
    float lmax = -1e30f;
    for (int l = tid; l < NLP1; l += 256) {
        const float4* kp = (const float4*)(qkv + hb + 512 + (size_t)l * QS);
        float d = 0.f;
#pragma unroll
        for (int j = 0; j < HDIM / 4; j++) {
            float4 kk = kp[j];
            d += sq[4 * j + 0] * kk.x + sq[4 * j + 1] * kk.y
               + sq[4 * j + 2] * kk.z + sq[4 * j + 3] * kk.w;
        }
        d *= 0.125f;
        sc[l] = d;
        lmax = fmaxf(lmax, d);
    }
    int lane = tid & 31, w = tid >> 5;
#pragma unroll
    for (int o = 16; o; o >>= 1) lmax = fmaxf(lmax, __shfl_xor_sync(0xffffffffu, lmax, o));
    if (lane == 0) red[w] = lmax;
    __syncthreads();
    if (tid == 0) {
        float m = red[0];
#pragma unroll
        for (int i = 1; i < 8; i++) m = fmaxf(m, red[i]);
        red[0] = m;
    }
    __syncthreads();
    float m = red[0];
    __syncthreads();
    float lsum = 0.f;
    for (int l = tid; l < NLP1; l += 256) {
        float e = __expf(sc[l] - m);
        sc[l] = e;
        lsum += e;
    }
#pragma unroll
    for (int o = 16; o; o >>= 1) lsum += __shfl_xor_sync(0xffffffffu, lsum, o);
    if (lane == 0) red[w] = lsum;
    __syncthreads();
    if (tid == 0) {
        float s = 0.f;
#pragma unroll
        for (int i = 0; i < 8; i++) s += red[i];
        red[0] = s;
    }
    __syncthreads();
    float Zinv = 1.f / red[0];
    int d = tid & 63, g = tid >> 6;
    float acc = 0.f;
    for (int l = g; l < NLP1; l += 4)
        acc += sc[l] * qkv[hb + 1024 + (size_t)l * QS + d];
    part[g][d] = acc;
    __syncthreads();
    if (tid < HDIM)
        attr[(size_t)b * NH + h * HDIM + tid] =
            (part[0][tid] + part[1][tid] + part[2][tid] + part[3][tid]) * Zinv;
}

// ---------------- star output GEMM + leaky ----------------
__global__ __launch_bounds__(256) void star_out_k(
    const float* __restrict__ attr, const float* __restrict__ w,
    const float* __restrict__ bias, float* __restrict__ relay)
{
    __shared__ float sa[512];
    __shared__ float red[4][64];
    int b = blockIdx.y, cx = blockIdx.x;
    int t = threadIdx.x;
    sa[t]       = attr[b * NH + t];
    sa[t + 256] = attr[b * NH + t + 256];
    __syncthreads();
    int col = cx * 64 + (t & 63), g = t >> 6;
    float acc = 0.f;
    const float* wp = w + (size_t)(g * 128) * NH + col;
#pragma unroll 4
    for (int kk = 0; kk < 128; kk++)
        acc += sa[g * 128 + kk] * wp[(size_t)kk * NH];
    red[g][t & 63] = acc;
    __syncthreads();
    if (t < 64) {
        float a = red[0][t] + red[1][t] + red[2][t] + red[3][t] + bias[cx * 64 + t];
        relay[b * NH + cx * 64 + t] = a > 0.f ? a : 0.2f * a;
    }
}

// ---------------- final from tile partials + relay ----------------
__global__ void final_fin2_k(const float* __restrict__ partmax,
                             const float* __restrict__ relay, float* __restrict__ out)
{
    int b = blockIdx.x, j = threadIdx.x;   // 512 threads
    float m = -3.4e38f;
#pragma unroll
    for (int t = 0; t < 16; t++) m = fmaxf(m, partmax[(size_t)(b * 16 + t) * NH + j]);
    out[b * NH + j] = 0.5f * (relay[b * NH + j] + m);
}

// =====================================================================
//  host launch
// =====================================================================
extern "C" void kernel_launch(void* const* d_in, const int* in_sizes, int n_in,
                              void* d_out, int out_size)
{
    const float* data    = (const float*)d_in[0];
    const float* fc_w    = (const float*)d_in[1];
    const float* fc_b    = (const float*)d_in[2];
    const float* pos_emb = (const float*)d_in[3];
    const float* ln_g    = (const float*)d_in[4];
    const float* ln_b    = (const float*)d_in[5];
    const float* wq      = (const float*)d_in[6];
    const float* wk      = (const float*)d_in[7];
    const float* wv      = (const float*)d_in[8];
    const float* bq      = (const float*)d_in[9];
    const float* bk      = (const float*)d_in[10];
    const float* bv      = (const float*)d_in[11];
    const float* ring_wo = (const float*)d_in[12];
    const float* ring_bo = (const float*)d_in[13];
    const float* star_wo = (const float*)d_in[14];
    const float* star_bo = (const float*)d_in[15];
    float* out = (float*)d_out;

    float *nodes, *qkv, *relay, *attr, *part;
    __half *a16, *b16;
    cudaGetSymbolAddress((void**)&nodes, g_nodes);
    cudaGetSymbolAddress((void**)&qkv,   g_qkv);
    cudaGetSymbolAddress((void**)&relay, g_relay);
    cudaGetSymbolAddress((void**)&attr,  g_attr);
    cudaGetSymbolAddress((void**)&part,  g_part);
    cudaGetSymbolAddress((void**)&a16,   g_a16);
    cudaGetSymbolAddress((void**)&b16,   g_b16);
    float* partSum = part;
    float* partMax = part + (size_t)128 * NH;

    static bool init_done = false;
    static cudaStream_t s2;
    static cudaEvent_t evFork[NLAYERS], evJoin[NLAYERS], evFork0, evConvB;
    if (!init_done) {
        cudaFuncSetAttribute(mmagemm16<0,1>, cudaFuncAttributeMaxDynamicSharedMemorySize, SMEM_GEMM);
        cudaFuncSetAttribute(mmagemm16<1,0>, cudaFuncAttributeMaxDynamicSharedMemorySize, SMEM_GEMM);
        cudaFuncSetAttribute(mmagemm16<2,0>, cudaFuncAttributeMaxDynamicSharedMemorySize, SMEM_GEMM);
        cudaFuncSetAttribute(mmagemm16<2,2>, cudaFuncAttributeMaxDynamicSharedMemorySize, SMEM_GEMM);
        cudaStreamCreateWithFlags(&s2, cudaStreamNonBlocking);
        for (int i = 0; i < NLAYERS; i++) {
            cudaEventCreateWithFlags(&evFork[i], cudaEventDisableTiming);
            cudaEventCreateWithFlags(&evJoin[i], cudaEventDisableTiming);
        }
        cudaEventCreateWithFlags(&evFork0, cudaEventDisableTiming);
        cudaEventCreateWithFlags(&evConvB, cudaEventDisableTiming);
        init_done = true;
    }
    cudaStream_t s0 = (cudaStream_t)0;

    const int M_nodes = NB * NL;     // 16384
    const int M_xy    = NB * NLP1;   // 16392
    dim3 gN(4, M_nodes / 128);       // (4,128)  N=512
    dim3 gQKV(12, (M_xy + 127) / 128); // (12,129) N=1536

    // ---- fork s2 from origin (graph-capture rule); convB on s2 ∥ convA on s0
    cudaEventRecord(evFork0, s0);
    cudaStreamWaitEvent(s2, evFork0, 0);
    convB_all_k<<<dim3(16, 16, 1 + NLAYERS * 4), 256, 0, s2>>>(fc_w, wq, wk, wv, ring_wo, b16);
    cudaEventRecord(evConvB, s2);
    convA16_k<<<(M_nodes * 128 + 255) / 256, 256>>>(data, a16, M_nodes * 128);
    cudaStreamWaitEvent(s0, evConvB, 0);

    // ---- embeddings: GEMM with fused per-tile column sums -> relay ----
    mmagemm16<0,1><<<gN, 256, SMEM_GEMM>>>(a16, b16, fc_b, fc_b, fc_b, pos_emb,
                                           nodes, M_nodes, NH, partSum);
    relay_fin2_k<<<NB, NH>>>(partSum, relay);

    for (int i = 0; i < NLAYERS; i++) {
        size_t bOff = (size_t)i * 512;
        __half* slot  = b16 + (size_t)(512 + i * 2048) * NH;
        __half* slotO = slot + (size_t)1536 * NH;

        if (i > 0) cudaStreamWaitEvent(s0, evJoin[i - 1], 0);  // relay ready
        ln_concat_k<<<(NB * NLP1) / 8, 256>>>(nodes, relay, ln_g + bOff, ln_b + bOff, a16);

        mmagemm16<1,0><<<gQKV, 256, SMEM_GEMM>>>(a16, slot, bq + bOff, bk + bOff,
                                                 bv + bOff, nullptr, qkv, M_xy, QS, nullptr);

        // fork: star branch on s2 (depends only on qkv), overlaps ring branch
        cudaEventRecord(evFork[i], s0);
        cudaStreamWaitEvent(s2, evFork[i], 0);
        star_attn_k<<<NB * NHEADS, 256, 0, s2>>>(qkv, attr);
        star_out_k<<<dim3(8, NB), 256, 0, s2>>>(attr, star_wo + (size_t)i * 512 * 512,
                                                star_bo + bOff, relay);
        cudaEventRecord(evJoin[i], s2);

        // 4-l-per-warp ring attention: NB*NHEADS*512 warps / 8 per block
        ring_attn_k<<<NB * NHEADS * 512 / 8, 256>>>(qkv, a16);
        if (i < NLAYERS - 1) {
            mmagemm16<2,0><<<gN, 256, SMEM_GEMM>>>(a16, slotO, ring_bo + bOff, ring_bo + bOff,
                                                   ring_bo + bOff, nullptr, nodes, M_nodes, NH,
                                                   nullptr);
        } else {
            mmagemm16<2,2><<<gN, 256, SMEM_GEMM>>>(a16, slotO, ring_bo + bOff, ring_bo + bOff,
                                                   ring_bo + bOff, nullptr, nodes, M_nodes, NH,
                                                   partMax);
        }
    }

    cudaStreamWaitEvent(s0, evJoin[NLAYERS - 1], 0);           // relay ready
    final_fin2_k<<<NB, NH>>>(partMax, relay, out);
}